// round 9
// baseline (speedup 1.0000x reference)
#include <cuda_runtime.h>
#include <cuda_bf16.h>
#include <cstdint>

#define N_NODES 10000
#define DIN 128
#define H1 8
#define F1 64
#define C1 512            // H1*F1
#define E0 80000
#define NE (2*E0 + N_NODES)   // 170000
#define F2 64
#define NEG_SLOPE 0.2f
#define FULL 0xffffffffu

// ---------------- scratch (static device globals; no allocation) -------------
static __device__ int      g_src[NE];
static __device__ int      g_dst[NE];
static __device__ int      g_cnt[N_NODES];
static __device__ int      g_cursor[N_NODES];
static __device__ int      g_rowptr[N_NODES + 1];
static __device__ int      g_nbr[NE];              // CSR by dst: src indices
static __device__ uint32_t g_XH[N_NODES*(DIN/2)];  // x split, [n][kpair]
static __device__ uint32_t g_XL[N_NODES*(DIN/2)];
static __device__ uint32_t g_B1H[(DIN/2)*C1];      // W1 repacked+split, kpair-major
static __device__ uint32_t g_B1L[(DIN/2)*C1];
static __device__ uint32_t g_B2H[(C1/2)*F2];       // W2 split, kpair-major
static __device__ uint32_t g_B2L[(C1/2)*F2];
static __device__ float    g_proj1[N_NODES*C1];
static __device__ float    g_as1[N_NODES*H1];
static __device__ float    g_an1[N_NODES*H1];
static __device__ uint32_t g_HH[N_NODES*(C1/2)];   // layer-1 output, split bf16 pairs
static __device__ uint32_t g_HL[N_NODES*(C1/2)];
static __device__ float    g_proj2[N_NODES*F2];
static __device__ float    g_as2[N_NODES];
static __device__ float    g_an2[N_NODES];

__device__ __forceinline__ void split_pack(float v0, float v1,
                                           uint32_t& hi, uint32_t& lo) {
    __nv_bfloat162 h2 = __floats2bfloat162_rn(v0, v1);
    float r0 = v0 - __low2float(h2);
    float r1 = v1 - __high2float(h2);
    __nv_bfloat162 l2 = __floats2bfloat162_rn(r0, r1);
    hi = *(const uint32_t*)&h2;
    lo = *(const uint32_t*)&l2;
}

// ---------------- prep: edges + degree + W1/W2/x splits -----------------------
#define NXP (N_NODES*(DIN/2))    // 640000
__global__ void prep_kernel(const int* __restrict__ e32,
                            const float* __restrict__ W1,
                            const float* __restrict__ W2,
                            const float* __restrict__ x) {
    int i = blockIdx.x * blockDim.x + threadIdx.x;
    if (i < NE) {
        bool is64 = (e32[1] == 0) && (e32[3] == 0) && (e32[5] == 0) && (e32[7] == 0);
        int s, d;
        if (i < NE - N_NODES) {
            int j  = (i < E0) ? i : (i - E0);
            int si = (i < E0) ? j : (E0 + j);
            int di = (i < E0) ? (E0 + j) : j;
            s = is64 ? e32[2*si] : e32[si];
            d = is64 ? e32[2*di] : e32[di];
        } else {
            s = i - (NE - N_NODES); d = s;
        }
        s = min(max(s, 0), N_NODES - 1);
        d = min(max(d, 0), N_NODES - 1);
        g_src[i] = s; g_dst[i] = d;
        atomicAdd(&g_cnt[d], 1);
    }
    // x (N,DIN) -> split [n][DIN/2]
    if (i < NXP) {
        float2 v = *(const float2*)&x[2*i];       // i = n*(DIN/2) + kp
        split_pack(v.x, v.y, g_XH[i], g_XL[i]);
    }
    // W1 (H,Din,F1) -> kpair-major split [DIN/2][C1]
    if (i < (DIN/2)*C1) {
        int kp = i / C1, c = i % C1;
        int h = c >> 6, f = c & 63;
        float v0 = W1[(h*DIN + 2*kp)*F1 + f];
        float v1 = W1[(h*DIN + 2*kp + 1)*F1 + f];
        split_pack(v0, v1, g_B1H[i], g_B1L[i]);
    }
    // W2 (C1,F2) -> kpair-major split [C1/2][F2]
    if (i < (C1/2)*F2) {
        int kp = i / F2, c = i % F2;
        float v0 = W2[(2*kp)*F2 + c];
        float v1 = W2[(2*kp + 1)*F2 + c];
        split_pack(v0, v1, g_B2H[i], g_B2L[i]);
    }
}

// ---------------- exclusive scan of in-degrees (single block) ----------------
__global__ void scan_kernel() {
    __shared__ int ssum[1024];
    const int t = threadIdx.x;
    const int per = (N_NODES + 1023) / 1024;   // 10
    int base = t * per;
    int loc[16];
    int s = 0;
#pragma unroll
    for (int i = 0; i < per; i++) {
        int idx = base + i;
        int v = (idx < N_NODES) ? g_cnt[idx] : 0;
        loc[i] = v; s += v;
    }
    ssum[t] = s;
    __syncthreads();
    for (int off = 1; off < 1024; off <<= 1) {
        int v = (t >= off) ? ssum[t - off] : 0;
        __syncthreads();
        ssum[t] += v;
        __syncthreads();
    }
    int run = (t > 0) ? ssum[t - 1] : 0;
#pragma unroll
    for (int i = 0; i < per; i++) {
        int idx = base + i;
        if (idx < N_NODES) { g_rowptr[idx] = run; g_cursor[idx] = run; run += loc[i]; }
    }
    if (t == 1023) g_rowptr[N_NODES] = NE;
}

__global__ void fill_csr() {
    int e = blockIdx.x * blockDim.x + threadIdx.x;
    if (e >= NE) return;
    int d = g_dst[e];
    int slot = atomicAdd(&g_cursor[d], 1);   // cursor pre-seeded with rowptr
    g_nbr[slot] = g_src[e];
}

// ---------------- bf16x3 tensor-core MMA (m16n8k16) --------------------------
#define MMA_BF16(D, A0, A1, A2, A3, B0, B1) \
    asm("mma.sync.aligned.m16n8k16.row.col.f32.bf16.bf16.f32 " \
        "{%0,%1,%2,%3}, {%4,%5,%6,%7}, {%8,%9}, {%0,%1,%2,%3};" \
        : "+f"(D[0]), "+f"(D[1]), "+f"(D[2]), "+f"(D[3]) \
        : "r"(A0), "r"(A1), "r"(A2), "r"(A3), "r"(B0), "r"(B1))

// ---------------- GEMM1: 128x64 tile, pre-split A and B, fused alpha1 --------
__global__ __launch_bounds__(256) void gemm1_kernel(const float* __restrict__ a1) {
    __shared__ uint32_t AsH[128][12], AsL[128][12];
    __shared__ uint32_t BsH[64][12],  BsL[64][12];
    __shared__ float sAs[64], sAn[64];
    __shared__ float salS[128][2], salN[128][2];

    const int tid = threadIdx.x;
    const int lane = tid & 31, wid = tid >> 5;
    const int wm = wid >> 1, wn = wid & 1;
    const int g = lane >> 2, tig = lane & 3;
    const int row0 = blockIdx.y * 128;
    const int h = blockIdx.x;
    const int col0 = h * 64;
    const int M = N_NODES;

    if (tid < 64) {
        sAs[tid] = __ldg(&a1[h*2*F1 + tid]);
        sAn[tid] = __ldg(&a1[h*2*F1 + F1 + tid]);
    }

    float acc[2][4][4];
#pragma unroll
    for (int mi = 0; mi < 2; mi++)
#pragma unroll
        for (int ni = 0; ni < 4; ni++)
#pragma unroll
            for (int q = 0; q < 4; q++) acc[mi][ni][q] = 0.f;

    for (int k0 = 0; k0 < DIN; k0 += 16) {
        const int kpb = k0 >> 1;     // kpair base
        // A tile: pre-split, 4 entries/thread from each plane
#pragma unroll
        for (int t = 0; t < 4; t++) {
            int idx = tid + t*256;
            int r = idx >> 3, kk = idx & 7;
            int grow = row0 + r;
            if (grow < M) {
                size_t gi = (size_t)grow*(DIN/2) + kpb + kk;
                AsH[r][kk] = g_XH[gi];
                AsL[r][kk] = g_XL[gi];
            } else {
                AsH[r][kk] = 0u; AsL[r][kk] = 0u;
            }
        }
        // B tile: pre-split
#pragma unroll
        for (int t = 0; t < 2; t++) {
            int idx = tid + t*256;
            int kk = idx >> 6, c = idx & 63;
            size_t gi = (size_t)(kpb + kk)*C1 + col0 + c;
            BsH[c][kk] = g_B1H[gi];
            BsL[c][kk] = g_B1L[gi];
        }
        __syncthreads();

        uint32_t bh[4][2], bl[4][2];
#pragma unroll
        for (int ni = 0; ni < 4; ni++) {
            int c = wn*32 + ni*8 + g;
            bh[ni][0] = BsH[c][tig];     bh[ni][1] = BsH[c][tig + 4];
            bl[ni][0] = BsL[c][tig];     bl[ni][1] = BsL[c][tig + 4];
        }
#pragma unroll
        for (int mi = 0; mi < 2; mi++) {
            int r = wm*32 + mi*16 + g;
            uint32_t ah0 = AsH[r][tig],     ah1 = AsH[r + 8][tig];
            uint32_t ah2 = AsH[r][tig + 4], ah3 = AsH[r + 8][tig + 4];
            uint32_t al0 = AsL[r][tig],     al1 = AsL[r + 8][tig];
            uint32_t al2 = AsL[r][tig + 4], al3 = AsL[r + 8][tig + 4];
#pragma unroll
            for (int ni = 0; ni < 4; ni++) {
                MMA_BF16(acc[mi][ni], ah0, ah1, ah2, ah3, bh[ni][0], bh[ni][1]);
                MMA_BF16(acc[mi][ni], ah0, ah1, ah2, ah3, bl[ni][0], bl[ni][1]);
                MMA_BF16(acc[mi][ni], al0, al1, al2, al3, bh[ni][0], bh[ni][1]);
            }
        }
        __syncthreads();
    }

    // epilogue: store proj1 + fused alpha1
#pragma unroll
    for (int mi = 0; mi < 2; mi++) {
        float s0 = 0.f, s8 = 0.f, n0 = 0.f, n8 = 0.f;
        int growA = row0 + wm*32 + mi*16 + g;
        int growB = growA + 8;
#pragma unroll
        for (int ni = 0; ni < 4; ni++) {
            float c0 = acc[mi][ni][0], c1 = acc[mi][ni][1];
            float c2 = acc[mi][ni][2], c3 = acc[mi][ni][3];
            int cl = wn*32 + ni*8 + 2*tig;
            if (growA < M)
                *(float2*)&g_proj1[(size_t)growA*C1 + col0 + cl] = make_float2(c0, c1);
            if (growB < M)
                *(float2*)&g_proj1[(size_t)growB*C1 + col0 + cl] = make_float2(c2, c3);
            float as0 = sAs[cl], as1 = sAs[cl + 1];
            float an0 = sAn[cl], an1 = sAn[cl + 1];
            s0 += c0*as0 + c1*as1;  n0 += c0*an0 + c1*an1;
            s8 += c2*as0 + c3*as1;  n8 += c2*an0 + c3*an1;
        }
#pragma unroll
        for (int o = 1; o <= 2; o <<= 1) {
            s0 += __shfl_xor_sync(FULL, s0, o);
            s8 += __shfl_xor_sync(FULL, s8, o);
            n0 += __shfl_xor_sync(FULL, n0, o);
            n8 += __shfl_xor_sync(FULL, n8, o);
        }
        if (tig == 0) {
            int rl = wm*32 + mi*16 + g;
            salS[rl][wn] = s0;  salN[rl][wn] = n0;
            salS[rl + 8][wn] = s8;  salN[rl + 8][wn] = n8;
        }
    }
    __syncthreads();
    if (tid < 128) {
        int grow = row0 + tid;
        if (grow < M) {
            g_as1[grow*H1 + h] = salS[tid][0] + salS[tid][1];
            g_an1[grow*H1 + h] = salN[tid][0] + salN[tid][1];
        }
    }
}

// ---------------- GEMM2: bf16x3 MMA, pre-split A (from gather1) + B ----------
__global__ __launch_bounds__(256) void gemm2_kernel(const float* __restrict__ a2) {
    __shared__ uint32_t AsH[128][12], AsL[128][12];
    __shared__ uint32_t BsH[64][12],  BsL[64][12];
    __shared__ float sAs[64], sAn[64];
    __shared__ float salS[128][2], salN[128][2];

    const int tid = threadIdx.x;
    const int lane = tid & 31, wid = tid >> 5;
    const int wm = wid >> 1, wn = wid & 1;
    const int g = lane >> 2, tig = lane & 3;
    const int row0 = blockIdx.y * 128;
    const int M = N_NODES;

    if (tid < 64) {
        sAs[tid] = __ldg(&a2[tid]);
        sAn[tid] = __ldg(&a2[F2 + tid]);
    }

    float acc[2][4][4];
#pragma unroll
    for (int mi = 0; mi < 2; mi++)
#pragma unroll
        for (int ni = 0; ni < 4; ni++)
#pragma unroll
            for (int q = 0; q < 4; q++) acc[mi][ni][q] = 0.f;

    for (int k0 = 0; k0 < C1; k0 += 16) {
        const int kpb = k0 >> 1;
#pragma unroll
        for (int t = 0; t < 4; t++) {
            int idx = tid + t*256;
            int r = idx >> 3, kk = idx & 7;
            int grow = row0 + r;
            if (grow < M) {
                size_t gi = (size_t)grow*(C1/2) + kpb + kk;
                AsH[r][kk] = g_HH[gi];
                AsL[r][kk] = g_HL[gi];
            } else {
                AsH[r][kk] = 0u; AsL[r][kk] = 0u;
            }
        }
#pragma unroll
        for (int t = 0; t < 2; t++) {
            int idx = tid + t*256;
            int kk = idx >> 6, c = idx & 63;
            size_t gi = (size_t)(kpb + kk)*F2 + c;
            BsH[c][kk] = g_B2H[gi];
            BsL[c][kk] = g_B2L[gi];
        }
        __syncthreads();

        uint32_t bh[4][2], bl[4][2];
#pragma unroll
        for (int ni = 0; ni < 4; ni++) {
            int c = wn*32 + ni*8 + g;
            bh[ni][0] = BsH[c][tig];     bh[ni][1] = BsH[c][tig + 4];
            bl[ni][0] = BsL[c][tig];     bl[ni][1] = BsL[c][tig + 4];
        }
#pragma unroll
        for (int mi = 0; mi < 2; mi++) {
            int r = wm*32 + mi*16 + g;
            uint32_t ah0 = AsH[r][tig],     ah1 = AsH[r + 8][tig];
            uint32_t ah2 = AsH[r][tig + 4], ah3 = AsH[r + 8][tig + 4];
            uint32_t al0 = AsL[r][tig],     al1 = AsL[r + 8][tig];
            uint32_t al2 = AsL[r][tig + 4], al3 = AsL[r + 8][tig + 4];
#pragma unroll
            for (int ni = 0; ni < 4; ni++) {
                MMA_BF16(acc[mi][ni], ah0, ah1, ah2, ah3, bh[ni][0], bh[ni][1]);
                MMA_BF16(acc[mi][ni], ah0, ah1, ah2, ah3, bl[ni][0], bl[ni][1]);
                MMA_BF16(acc[mi][ni], al0, al1, al2, al3, bh[ni][0], bh[ni][1]);
            }
        }
        __syncthreads();
    }

#pragma unroll
    for (int mi = 0; mi < 2; mi++) {
        float s0 = 0.f, s8 = 0.f, n0 = 0.f, n8 = 0.f;
        int growA = row0 + wm*32 + mi*16 + g;
        int growB = growA + 8;
#pragma unroll
        for (int ni = 0; ni < 4; ni++) {
            float c0 = acc[mi][ni][0], c1 = acc[mi][ni][1];
            float c2 = acc[mi][ni][2], c3 = acc[mi][ni][3];
            int cl = wn*32 + ni*8 + 2*tig;
            if (growA < M)
                *(float2*)&g_proj2[(size_t)growA*F2 + cl] = make_float2(c0, c1);
            if (growB < M)
                *(float2*)&g_proj2[(size_t)growB*F2 + cl] = make_float2(c2, c3);
            float as0 = sAs[cl], as1 = sAs[cl + 1];
            float an0 = sAn[cl], an1 = sAn[cl + 1];
            s0 += c0*as0 + c1*as1;  n0 += c0*an0 + c1*an1;
            s8 += c2*as0 + c3*as1;  n8 += c2*an0 + c3*an1;
        }
#pragma unroll
        for (int o = 1; o <= 2; o <<= 1) {
            s0 += __shfl_xor_sync(FULL, s0, o);
            s8 += __shfl_xor_sync(FULL, s8, o);
            n0 += __shfl_xor_sync(FULL, n0, o);
            n8 += __shfl_xor_sync(FULL, n8, o);
        }
        if (tig == 0) {
            int rl = wm*32 + mi*16 + g;
            salS[rl][wn] = s0;  salN[rl][wn] = n0;
            salS[rl + 8][wn] = s8;  salN[rl + 8][wn] = n8;
        }
    }
    __syncthreads();
    if (tid < 128) {
        int grow = row0 + tid;
        if (grow < M) {
            g_as2[grow] = salS[tid][0] + salS[tid][1];
            g_an2[grow] = salN[tid][0] + salN[tid][1];
        }
    }
}

// ---------------- fused gather1: softmax + agg + ELU + bf16-split store ------
__global__ void gather1() {
    int t = blockIdx.x * blockDim.x + threadIdx.x;
    int w = t >> 5, lane = t & 31;
    if (w >= N_NODES*H1) return;
    int n = w >> 3, h = w & 7;
    int beg = g_rowptr[n], end = g_rowptr[n + 1];
    float as = g_as1[n*H1 + h];

    float mx = -3.0e38f;
    for (int i = beg + lane; i < end; i += 32) {
        float v = as + g_an1[g_nbr[i]*H1 + h];
        v = (v >= 0.f) ? v : NEG_SLOPE*v;
        mx = fmaxf(mx, v);
    }
#pragma unroll
    for (int o = 16; o; o >>= 1) mx = fmaxf(mx, __shfl_xor_sync(FULL, mx, o));

    const int half = lane >> 4;
    const int fl = (lane & 15) * 4;
    const float* projh = g_proj1 + h*F1 + fl;
    float a0 = 0.f, a1v = 0.f, a2v = 0.f, a3 = 0.f, den = 0.f;
    for (int base = beg; base < end; base += 32) {
        int i = base + lane;
        int s = 0; float wgt = 0.f;
        if (i < end) {
            s = g_nbr[i];
            float v = as + g_an1[s*H1 + h];
            v = (v >= 0.f) ? v : NEG_SLOPE*v;
            wgt = __expf(v - mx);
            den += wgt;
        }
        int cnt = min(32, end - base);
        if (cnt == 32) {
#pragma unroll
            for (int j = 0; j < 16; j++) {
                int sl = 2*j + half;
                float ww = __shfl_sync(FULL, wgt, sl);
                int ss = __shfl_sync(FULL, s, sl);
                float4 p = *(const float4*)&projh[(size_t)ss*C1];
                a0 += ww*p.x; a1v += ww*p.y; a2v += ww*p.z; a3 += ww*p.w;
            }
        } else {
            int jmax = (cnt + 1) >> 1;
            for (int j = 0; j < jmax; j++) {
                int sl = 2*j + half;
                float ww = __shfl_sync(FULL, wgt, sl);
                int ss = __shfl_sync(FULL, s, sl);
                float4 p = *(const float4*)&projh[(size_t)ss*C1];
                a0 += ww*p.x; a1v += ww*p.y; a2v += ww*p.z; a3 += ww*p.w;
            }
        }
    }
    a0  += __shfl_xor_sync(FULL, a0, 16);
    a1v += __shfl_xor_sync(FULL, a1v, 16);
    a2v += __shfl_xor_sync(FULL, a2v, 16);
    a3  += __shfl_xor_sync(FULL, a3, 16);
#pragma unroll
    for (int o = 16; o; o >>= 1) den += __shfl_xor_sync(FULL, den, o);
    if (lane < 16) {
        float inv = 1.f / den;
        a0 *= inv; a1v *= inv; a2v *= inv; a3 *= inv;
        a0  = (a0  > 0.f) ? a0  : expm1f(a0);
        a1v = (a1v > 0.f) ? a1v : expm1f(a1v);
        a2v = (a2v > 0.f) ? a2v : expm1f(a2v);
        a3  = (a3  > 0.f) ? a3  : expm1f(a3);
        // store split bf16 pairs for gemm2 (2 kpairs per thread)
        size_t kp0 = (size_t)n*(C1/2) + ((h*F1 + fl) >> 1);
        uint32_t h0, l0, h1, l1;
        split_pack(a0, a1v, h0, l0);
        split_pack(a2v, a3, h1, l1);
        g_HH[kp0] = h0;  g_HL[kp0] = l0;
        g_HH[kp0 + 1] = h1;  g_HL[kp0 + 1] = l1;
    }
}

// ---------------- fused gather layer 2 (H2=1, mean == identity) --------------
__global__ void gather2(float* __restrict__ out) {
    int t = blockIdx.x * blockDim.x + threadIdx.x;
    int w = t >> 5, lane = t & 31;
    if (w >= N_NODES) return;
    int n = w;
    int beg = g_rowptr[n], end = g_rowptr[n + 1];
    float as = g_as2[n];

    float mx = -3.0e38f;
    for (int i = beg + lane; i < end; i += 32) {
        float v = as + g_an2[g_nbr[i]];
        v = (v >= 0.f) ? v : NEG_SLOPE*v;
        mx = fmaxf(mx, v);
    }
#pragma unroll
    for (int o = 16; o; o >>= 1) mx = fmaxf(mx, __shfl_xor_sync(FULL, mx, o));

    const int half = lane >> 4;
    const int fl = (lane & 15) * 4;
    const float* projl = g_proj2 + fl;
    float a0 = 0.f, a1v = 0.f, a2v = 0.f, a3 = 0.f, den = 0.f;
    for (int base = beg; base < end; base += 32) {
        int i = base + lane;
        int s = 0; float wgt = 0.f;
        if (i < end) {
            s = g_nbr[i];
            float v = as + g_an2[s];
            v = (v >= 0.f) ? v : NEG_SLOPE*v;
            wgt = __expf(v - mx);
            den += wgt;
        }
        int cnt = min(32, end - base);
        if (cnt == 32) {
#pragma unroll
            for (int j = 0; j < 16; j++) {
                int sl = 2*j + half;
                float ww = __shfl_sync(FULL, wgt, sl);
                int ss = __shfl_sync(FULL, s, sl);
                float4 p = *(const float4*)&projl[(size_t)ss*F2];
                a0 += ww*p.x; a1v += ww*p.y; a2v += ww*p.z; a3 += ww*p.w;
            }
        } else {
            int jmax = (cnt + 1) >> 1;
            for (int j = 0; j < jmax; j++) {
                int sl = 2*j + half;
                float ww = __shfl_sync(FULL, wgt, sl);
                int ss = __shfl_sync(FULL, s, sl);
                float4 p = *(const float4*)&projl[(size_t)ss*F2];
                a0 += ww*p.x; a1v += ww*p.y; a2v += ww*p.z; a3 += ww*p.w;
            }
        }
    }
    a0  += __shfl_xor_sync(FULL, a0, 16);
    a1v += __shfl_xor_sync(FULL, a1v, 16);
    a2v += __shfl_xor_sync(FULL, a2v, 16);
    a3  += __shfl_xor_sync(FULL, a3, 16);
#pragma unroll
    for (int o = 16; o; o >>= 1) den += __shfl_xor_sync(FULL, den, o);
    if (lane < 16) {
        float inv = 1.f / den;
        *(float4*)&out[(size_t)n*F2 + fl] =
            make_float4(a0*inv, a1v*inv, a2v*inv, a3*inv);
    }
}

// ---------------- launch -------------------------------------------------------
extern "C" void kernel_launch(void* const* d_in, const int* in_sizes, int n_in,
                              void* d_out, int out_size) {
    const float* x     = (const float*)d_in[0];
    const int*   edges = (const int*)d_in[1];
    const float* W1    = (const float*)d_in[2];
    const float* a1    = (const float*)d_in[3];
    const float* W2    = (const float*)d_in[4];
    const float* a2    = (const float*)d_in[5];
    float* out = (float*)d_out;

    void* cnt_ptr = nullptr;
    cudaGetSymbolAddress(&cnt_ptr, g_cnt);
    cudaMemsetAsync(cnt_ptr, 0, N_NODES*sizeof(int));

    prep_kernel<<<(NXP + 255)/256, 256>>>(edges, W1, W2, x);
    scan_kernel<<<1, 1024>>>();
    fill_csr<<<(NE + 255)/256, 256>>>();

    // layer 1
    gemm1_kernel<<<dim3(H1, (N_NODES + 127)/128), 256>>>(a1);
    gather1<<<(N_NODES*H1*32 + 255)/256, 256>>>();

    // layer 2
    gemm2_kernel<<<dim3(1, (N_NODES + 127)/128), 256>>>(a2);
    gather2<<<(N_NODES*32 + 255)/256, 256>>>(out);
}

// round 10
// speedup vs baseline: 1.0132x; 1.0132x over previous
#include <cuda_runtime.h>
#include <cuda_bf16.h>
#include <cuda_fp16.h>
#include <cstdint>

#define N_NODES 10000
#define DIN 128
#define H1 8
#define F1 64
#define C1 512            // H1*F1
#define E0 80000
#define NE (2*E0 + N_NODES)   // 170000
#define F2 64
#define NEG_SLOPE 0.2f
#define FULL 0xffffffffu
#define NXP (N_NODES*(DIN/2))    // 640000

// ---------------- scratch (static device globals; no allocation) -------------
static __device__ int      g_src[NE];
static __device__ int      g_dst[NE];
static __device__ int      g_cnt[N_NODES];
static __device__ int      g_cursor[N_NODES];
static __device__ int      g_rowptr[N_NODES + 1];
static __device__ int      g_nbr[NE];              // CSR by dst: src indices
static __device__ uint32_t g_XH[NXP];              // x split, [n][kpair]
static __device__ uint32_t g_XL[NXP];
static __device__ uint32_t g_B1H[(DIN/2)*C1];      // W1 repacked+split, kpair-major
static __device__ uint32_t g_B1L[(DIN/2)*C1];
static __device__ __half2  g_P1h[N_NODES*(C1/2)];  // proj1 as fp16 pairs (gather feed)
static __device__ float    g_as1[N_NODES*H1];
static __device__ float    g_an1[N_NODES*H1];
static __device__ float    g_hbuf[N_NODES*C1];     // layer-1 output (post ELU), fp32
static __device__ float    g_p2part[4*N_NODES*F2]; // split-K partials for gemm2
static __device__ float    g_proj2[N_NODES*F2];
static __device__ float    g_as2[N_NODES];
static __device__ float    g_an2[N_NODES];

__device__ __forceinline__ void split_pack(float v0, float v1,
                                           uint32_t& hi, uint32_t& lo) {
    __nv_bfloat162 h2 = __floats2bfloat162_rn(v0, v1);
    float r0 = v0 - __low2float(h2);
    float r1 = v1 - __high2float(h2);
    __nv_bfloat162 l2 = __floats2bfloat162_rn(r0, r1);
    hi = *(const uint32_t*)&h2;
    lo = *(const uint32_t*)&l2;
}

// ---------------- prep: edges + degree + W1/x splits ---------------------------
__global__ void prep_kernel(const int* __restrict__ e32,
                            const float* __restrict__ W1,
                            const float* __restrict__ x) {
    int i = blockIdx.x * blockDim.x + threadIdx.x;
    if (i < NE) {
        bool is64 = (e32[1] == 0) && (e32[3] == 0) && (e32[5] == 0) && (e32[7] == 0);
        int s, d;
        if (i < NE - N_NODES) {
            int j  = (i < E0) ? i : (i - E0);
            int si = (i < E0) ? j : (E0 + j);
            int di = (i < E0) ? (E0 + j) : j;
            s = is64 ? e32[2*si] : e32[si];
            d = is64 ? e32[2*di] : e32[di];
        } else {
            s = i - (NE - N_NODES); d = s;
        }
        s = min(max(s, 0), N_NODES - 1);
        d = min(max(d, 0), N_NODES - 1);
        g_src[i] = s; g_dst[i] = d;
        atomicAdd(&g_cnt[d], 1);
    }
    // x (N,DIN) -> split [n][DIN/2]
    if (i < NXP) {
        float2 v = *(const float2*)&x[2*i];
        split_pack(v.x, v.y, g_XH[i], g_XL[i]);
    }
    // W1 (H,Din,F1) -> kpair-major split [DIN/2][C1]
    if (i < (DIN/2)*C1) {
        int kp = i / C1, c = i % C1;
        int h = c >> 6, f = c & 63;
        float v0 = W1[(h*DIN + 2*kp)*F1 + f];
        float v1 = W1[(h*DIN + 2*kp + 1)*F1 + f];
        split_pack(v0, v1, g_B1H[i], g_B1L[i]);
    }
}

// ---------------- exclusive scan of in-degrees (single block) ----------------
__global__ void scan_kernel() {
    __shared__ int ssum[1024];
    const int t = threadIdx.x;
    const int per = (N_NODES + 1023) / 1024;   // 10
    int base = t * per;
    int loc[16];
    int s = 0;
#pragma unroll
    for (int i = 0; i < per; i++) {
        int idx = base + i;
        int v = (idx < N_NODES) ? g_cnt[idx] : 0;
        loc[i] = v; s += v;
    }
    ssum[t] = s;
    __syncthreads();
    for (int off = 1; off < 1024; off <<= 1) {
        int v = (t >= off) ? ssum[t - off] : 0;
        __syncthreads();
        ssum[t] += v;
        __syncthreads();
    }
    int run = (t > 0) ? ssum[t - 1] : 0;
#pragma unroll
    for (int i = 0; i < per; i++) {
        int idx = base + i;
        if (idx < N_NODES) { g_rowptr[idx] = run; g_cursor[idx] = run; run += loc[i]; }
    }
    if (t == 1023) g_rowptr[N_NODES] = NE;
}

__global__ void fill_csr() {
    int e = blockIdx.x * blockDim.x + threadIdx.x;
    if (e >= NE) return;
    int d = g_dst[e];
    int slot = atomicAdd(&g_cursor[d], 1);   // cursor pre-seeded with rowptr
    g_nbr[slot] = g_src[e];
}

// ---------------- bf16x3 tensor-core MMA (m16n8k16) --------------------------
#define MMA_BF16(D, A0, A1, A2, A3, B0, B1) \
    asm("mma.sync.aligned.m16n8k16.row.col.f32.bf16.bf16.f32 " \
        "{%0,%1,%2,%3}, {%4,%5,%6,%7}, {%8,%9}, {%0,%1,%2,%3};" \
        : "+f"(D[0]), "+f"(D[1]), "+f"(D[2]), "+f"(D[3]) \
        : "r"(A0), "r"(A1), "r"(A2), "r"(A3), "r"(B0), "r"(B1))

// ---------------- GEMM1: 128x64 tile, pre-split A/B, fused alpha1 ------------
// proj1 stored as fp16 pairs (feeds gather1); alpha dots computed in fp32.
__global__ __launch_bounds__(256) void gemm1_kernel(const float* __restrict__ a1) {
    __shared__ uint32_t AsH[128][12], AsL[128][12];
    __shared__ uint32_t BsH[64][12],  BsL[64][12];
    __shared__ float sAs[64], sAn[64];
    __shared__ float salS[128][2], salN[128][2];

    const int tid = threadIdx.x;
    const int lane = tid & 31, wid = tid >> 5;
    const int wm = wid >> 1, wn = wid & 1;
    const int g = lane >> 2, tig = lane & 3;
    const int row0 = blockIdx.y * 128;
    const int h = blockIdx.x;
    const int col0 = h * 64;
    const int M = N_NODES;

    if (tid < 64) {
        sAs[tid] = __ldg(&a1[h*2*F1 + tid]);
        sAn[tid] = __ldg(&a1[h*2*F1 + F1 + tid]);
    }

    float acc[2][4][4];
#pragma unroll
    for (int mi = 0; mi < 2; mi++)
#pragma unroll
        for (int ni = 0; ni < 4; ni++)
#pragma unroll
            for (int q = 0; q < 4; q++) acc[mi][ni][q] = 0.f;

    for (int k0 = 0; k0 < DIN; k0 += 16) {
        const int kpb = k0 >> 1;
#pragma unroll
        for (int t = 0; t < 4; t++) {
            int idx = tid + t*256;
            int r = idx >> 3, kk = idx & 7;
            int grow = row0 + r;
            if (grow < M) {
                size_t gi = (size_t)grow*(DIN/2) + kpb + kk;
                AsH[r][kk] = g_XH[gi];
                AsL[r][kk] = g_XL[gi];
            } else {
                AsH[r][kk] = 0u; AsL[r][kk] = 0u;
            }
        }
#pragma unroll
        for (int t = 0; t < 2; t++) {
            int idx = tid + t*256;
            int kk = idx >> 6, c = idx & 63;
            size_t gi = (size_t)(kpb + kk)*C1 + col0 + c;
            BsH[c][kk] = g_B1H[gi];
            BsL[c][kk] = g_B1L[gi];
        }
        __syncthreads();

        uint32_t bh[4][2], bl[4][2];
#pragma unroll
        for (int ni = 0; ni < 4; ni++) {
            int c = wn*32 + ni*8 + g;
            bh[ni][0] = BsH[c][tig];     bh[ni][1] = BsH[c][tig + 4];
            bl[ni][0] = BsL[c][tig];     bl[ni][1] = BsL[c][tig + 4];
        }
#pragma unroll
        for (int mi = 0; mi < 2; mi++) {
            int r = wm*32 + mi*16 + g;
            uint32_t ah0 = AsH[r][tig],     ah1 = AsH[r + 8][tig];
            uint32_t ah2 = AsH[r][tig + 4], ah3 = AsH[r + 8][tig + 4];
            uint32_t al0 = AsL[r][tig],     al1 = AsL[r + 8][tig];
            uint32_t al2 = AsL[r][tig + 4], al3 = AsL[r + 8][tig + 4];
#pragma unroll
            for (int ni = 0; ni < 4; ni++) {
                MMA_BF16(acc[mi][ni], ah0, ah1, ah2, ah3, bh[ni][0], bh[ni][1]);
                MMA_BF16(acc[mi][ni], ah0, ah1, ah2, ah3, bl[ni][0], bl[ni][1]);
                MMA_BF16(acc[mi][ni], al0, al1, al2, al3, bh[ni][0], bh[ni][1]);
            }
        }
        __syncthreads();
    }

    // epilogue: fp16 proj1 store + fused alpha1 (fp32)
#pragma unroll
    for (int mi = 0; mi < 2; mi++) {
        float s0 = 0.f, s8 = 0.f, n0 = 0.f, n8 = 0.f;
        int growA = row0 + wm*32 + mi*16 + g;
        int growB = growA + 8;
#pragma unroll
        for (int ni = 0; ni < 4; ni++) {
            float c0 = acc[mi][ni][0], c1 = acc[mi][ni][1];
            float c2 = acc[mi][ni][2], c3 = acc[mi][ni][3];
            int cl = wn*32 + ni*8 + 2*tig;
            size_t cp = (size_t)(col0 + cl) >> 1;   // half2 column index
            if (growA < M)
                g_P1h[(size_t)growA*(C1/2) + cp] = __floats2half2_rn(c0, c1);
            if (growB < M)
                g_P1h[(size_t)growB*(C1/2) + cp] = __floats2half2_rn(c2, c3);
            float as0 = sAs[cl], as1 = sAs[cl + 1];
            float an0 = sAn[cl], an1 = sAn[cl + 1];
            s0 += c0*as0 + c1*as1;  n0 += c0*an0 + c1*an1;
            s8 += c2*as0 + c3*as1;  n8 += c2*an0 + c3*an1;
        }
#pragma unroll
        for (int o = 1; o <= 2; o <<= 1) {
            s0 += __shfl_xor_sync(FULL, s0, o);
            s8 += __shfl_xor_sync(FULL, s8, o);
            n0 += __shfl_xor_sync(FULL, n0, o);
            n8 += __shfl_xor_sync(FULL, n8, o);
        }
        if (tig == 0) {
            int rl = wm*32 + mi*16 + g;
            salS[rl][wn] = s0;  salN[rl][wn] = n0;
            salS[rl + 8][wn] = s8;  salN[rl + 8][wn] = n8;
        }
    }
    __syncthreads();
    if (tid < 128) {
        int grow = row0 + tid;
        if (grow < M) {
            g_as1[grow*H1 + h] = salS[tid][0] + salS[tid][1];
            g_an1[grow*H1 + h] = salN[tid][0] + salN[tid][1];
        }
    }
}

// ---------------- GEMM2 split-K SIMT: 64x64 tile, K-chunk 128 per z ----------
__global__ void gemm2_kernel(const float* __restrict__ B) {
    __shared__ __align__(16) float As[16][68];
    __shared__ __align__(16) float Bs[16][64];
    const float* A = g_hbuf;
    const int M = N_NODES, N = F2, K = C1;
    const int tid = threadIdx.x;
    const int tx = tid & 15, ty = tid >> 4;
    const int row0 = blockIdx.y * 64;
    const int kz0 = blockIdx.z * (K/4);
    float* C = g_p2part + (size_t)blockIdx.z * N_NODES * F2;
    float acc[4][4];
#pragma unroll
    for (int i = 0; i < 4; i++)
#pragma unroll
        for (int j = 0; j < 4; j++) acc[i][j] = 0.f;

    for (int k0 = kz0; k0 < kz0 + K/4; k0 += 16) {
#pragma unroll
        for (int l = 0; l < 4; l++) {
            int i = tid + l*256;
            int r = i >> 4, kk = i & 15;
            int gr = row0 + r;
            As[kk][r] = (gr < M) ? A[(size_t)gr*K + k0 + kk] : 0.f;
        }
        {
            int kk = tid >> 6, c = tid & 63;
            Bs[kk][c]      = B[(size_t)(k0 + kk)*N + c];
            Bs[kk + 4][c]  = B[(size_t)(k0 + kk + 4)*N + c];
            Bs[kk + 8][c]  = B[(size_t)(k0 + kk + 8)*N + c];
            Bs[kk + 12][c] = B[(size_t)(k0 + kk + 12)*N + c];
        }
        __syncthreads();
#pragma unroll
        for (int kk = 0; kk < 16; kk++) {
            float4 av = *(const float4*)&As[kk][ty*4];
            float4 bv = *(const float4*)&Bs[kk][tx*4];
            float a[4] = {av.x, av.y, av.z, av.w};
            float b[4] = {bv.x, bv.y, bv.z, bv.w};
#pragma unroll
            for (int i = 0; i < 4; i++)
#pragma unroll
                for (int j = 0; j < 4; j++) acc[i][j] += a[i]*b[j];
        }
        __syncthreads();
    }
#pragma unroll
    for (int i = 0; i < 4; i++) {
        int gr = row0 + ty*4 + i;
        if (gr < M) {
            *(float4*)&C[(size_t)gr*N + tx*4] =
                make_float4(acc[i][0], acc[i][1], acc[i][2], acc[i][3]);
        }
    }
}

// ---------------- combine split-K partials + attention (layer 2) -------------
__global__ void alpha2_combine(const float* __restrict__ a2) {
    int t = blockIdx.x * blockDim.x + threadIdx.x;
    int w = t >> 5, lane = t & 31;
    if (w >= N_NODES) return;
    const size_t NF = (size_t)N_NODES * F2;
    size_t base = (size_t)w*F2;
    float v0 = g_p2part[base + lane]        + g_p2part[NF + base + lane]
             + g_p2part[2*NF + base + lane] + g_p2part[3*NF + base + lane];
    float v1 = g_p2part[base + lane + 32]        + g_p2part[NF + base + lane + 32]
             + g_p2part[2*NF + base + lane + 32] + g_p2part[3*NF + base + lane + 32];
    g_proj2[base + lane] = v0;
    g_proj2[base + lane + 32] = v1;
    float s  = v0*a2[lane]      + v1*a2[lane + 32];
    float tn = v0*a2[F2 + lane] + v1*a2[F2 + lane + 32];
#pragma unroll
    for (int o = 16; o; o >>= 1) {
        s  += __shfl_xor_sync(FULL, s, o);
        tn += __shfl_xor_sync(FULL, tn, o);
    }
    if (!lane) { g_as2[w] = s; g_an2[w] = tn; }
}

// ---------------- fused gather1: fp16 features, fp32 weights -----------------
__global__ void gather1() {
    int t = blockIdx.x * blockDim.x + threadIdx.x;
    int w = t >> 5, lane = t & 31;
    if (w >= N_NODES*H1) return;
    int n = w >> 3, h = w & 7;
    int beg = g_rowptr[n], end = g_rowptr[n + 1];
    float as = g_as1[n*H1 + h];

    float mx = -3.0e38f;
    for (int i = beg + lane; i < end; i += 32) {
        float v = as + g_an1[g_nbr[i]*H1 + h];
        v = (v >= 0.f) ? v : NEG_SLOPE*v;
        mx = fmaxf(mx, v);
    }
#pragma unroll
    for (int o = 16; o; o >>= 1) mx = fmaxf(mx, __shfl_xor_sync(FULL, mx, o));

    const int half = lane >> 4;
    const int fl2 = (lane & 15) * 2;            // half2 offset within head slice
    const __half2* projh = g_P1h + h*(F1/2) + fl2;
    float a0 = 0.f, a1v = 0.f, a2v = 0.f, a3 = 0.f, den = 0.f;
    for (int base = beg; base < end; base += 32) {
        int i = base + lane;
        int s = 0; float wgt = 0.f;
        if (i < end) {
            s = g_nbr[i];
            float v = as + g_an1[s*H1 + h];
            v = (v >= 0.f) ? v : NEG_SLOPE*v;
            wgt = __expf(v - mx);
            den += wgt;
        }
        int cnt = min(32, end - base);
        if (cnt == 32) {
#pragma unroll
            for (int j = 0; j < 16; j++) {
                int sl = 2*j + half;
                float ww = __shfl_sync(FULL, wgt, sl);
                int ss = __shfl_sync(FULL, s, sl);
                uint2 u = *(const uint2*)&projh[(size_t)ss*(C1/2)];
                float2 f0 = __half22float2(*reinterpret_cast<__half2*>(&u.x));
                float2 f1 = __half22float2(*reinterpret_cast<__half2*>(&u.y));
                a0 += ww*f0.x; a1v += ww*f0.y; a2v += ww*f1.x; a3 += ww*f1.y;
            }
        } else {
            int jmax = (cnt + 1) >> 1;
            for (int j = 0; j < jmax; j++) {
                int sl = 2*j + half;
                float ww = __shfl_sync(FULL, wgt, sl);
                int ss = __shfl_sync(FULL, s, sl);
                uint2 u = *(const uint2*)&projh[(size_t)ss*(C1/2)];
                float2 f0 = __half22float2(*reinterpret_cast<__half2*>(&u.x));
                float2 f1 = __half22float2(*reinterpret_cast<__half2*>(&u.y));
                a0 += ww*f0.x; a1v += ww*f0.y; a2v += ww*f1.x; a3 += ww*f1.y;
            }
        }
    }
    a0  += __shfl_xor_sync(FULL, a0, 16);
    a1v += __shfl_xor_sync(FULL, a1v, 16);
    a2v += __shfl_xor_sync(FULL, a2v, 16);
    a3  += __shfl_xor_sync(FULL, a3, 16);
#pragma unroll
    for (int o = 16; o; o >>= 1) den += __shfl_xor_sync(FULL, den, o);
    if (lane < 16) {
        float inv = 1.f / den;
        a0 *= inv; a1v *= inv; a2v *= inv; a3 *= inv;
        a0  = (a0  > 0.f) ? a0  : expm1f(a0);
        a1v = (a1v > 0.f) ? a1v : expm1f(a1v);
        a2v = (a2v > 0.f) ? a2v : expm1f(a2v);
        a3  = (a3  > 0.f) ? a3  : expm1f(a3);
        *(float4*)&g_hbuf[(size_t)n*C1 + h*F1 + fl2*2] = make_float4(a0, a1v, a2v, a3);
    }
}

// ---------------- fused gather layer 2 (fp32 features) -----------------------
__global__ void gather2(float* __restrict__ out) {
    int t = blockIdx.x * blockDim.x + threadIdx.x;
    int w = t >> 5, lane = t & 31;
    if (w >= N_NODES) return;
    int n = w;
    int beg = g_rowptr[n], end = g_rowptr[n + 1];
    float as = g_as2[n];

    float mx = -3.0e38f;
    for (int i = beg + lane; i < end; i += 32) {
        float v = as + g_an2[g_nbr[i]];
        v = (v >= 0.f) ? v : NEG_SLOPE*v;
        mx = fmaxf(mx, v);
    }
#pragma unroll
    for (int o = 16; o; o >>= 1) mx = fmaxf(mx, __shfl_xor_sync(FULL, mx, o));

    const int half = lane >> 4;
    const int fl = (lane & 15) * 4;
    const float* projl = g_proj2 + fl;
    float a0 = 0.f, a1v = 0.f, a2v = 0.f, a3 = 0.f, den = 0.f;
    for (int base = beg; base < end; base += 32) {
        int i = base + lane;
        int s = 0; float wgt = 0.f;
        if (i < end) {
            s = g_nbr[i];
            float v = as + g_an2[s];
            v = (v >= 0.f) ? v : NEG_SLOPE*v;
            wgt = __expf(v - mx);
            den += wgt;
        }
        int cnt = min(32, end - base);
        if (cnt == 32) {
#pragma unroll
            for (int j = 0; j < 16; j++) {
                int sl = 2*j + half;
                float ww = __shfl_sync(FULL, wgt, sl);
                int ss = __shfl_sync(FULL, s, sl);
                float4 p = *(const float4*)&projl[(size_t)ss*F2];
                a0 += ww*p.x; a1v += ww*p.y; a2v += ww*p.z; a3 += ww*p.w;
            }
        } else {
            int jmax = (cnt + 1) >> 1;
            for (int j = 0; j < jmax; j++) {
                int sl = 2*j + half;
                float ww = __shfl_sync(FULL, wgt, sl);
                int ss = __shfl_sync(FULL, s, sl);
                float4 p = *(const float4*)&projl[(size_t)ss*F2];
                a0 += ww*p.x; a1v += ww*p.y; a2v += ww*p.z; a3 += ww*p.w;
            }
        }
    }
    a0  += __shfl_xor_sync(FULL, a0, 16);
    a1v += __shfl_xor_sync(FULL, a1v, 16);
    a2v += __shfl_xor_sync(FULL, a2v, 16);
    a3  += __shfl_xor_sync(FULL, a3, 16);
#pragma unroll
    for (int o = 16; o; o >>= 1) den += __shfl_xor_sync(FULL, den, o);
    if (lane < 16) {
        float inv = 1.f / den;
        *(float4*)&out[(size_t)n*F2 + fl] =
            make_float4(a0*inv, a1v*inv, a2v*inv, a3*inv);
    }
}

// ---------------- launch -------------------------------------------------------
extern "C" void kernel_launch(void* const* d_in, const int* in_sizes, int n_in,
                              void* d_out, int out_size) {
    const float* x     = (const float*)d_in[0];
    const int*   edges = (const int*)d_in[1];
    const float* W1    = (const float*)d_in[2];
    const float* a1    = (const float*)d_in[3];
    const float* W2    = (const float*)d_in[4];
    const float* a2    = (const float*)d_in[5];
    float* out = (float*)d_out;

    void* cnt_ptr = nullptr;
    cudaGetSymbolAddress(&cnt_ptr, g_cnt);
    cudaMemsetAsync(cnt_ptr, 0, N_NODES*sizeof(int));

    prep_kernel<<<(NXP + 255)/256, 256>>>(edges, W1, x);
    scan_kernel<<<1, 1024>>>();
    fill_csr<<<(NE + 255)/256, 256>>>();

    // layer 1
    gemm1_kernel<<<dim3(H1, (N_NODES + 127)/128), 256>>>(a1);
    gather1<<<(N_NODES*H1*32 + 255)/256, 256>>>();

    // layer 2
    gemm2_kernel<<<dim3(1, (N_NODES + 63)/64, 4), 256>>>(W2);
    alpha2_combine<<<(N_NODES*32 + 255)/256, 256>>>(a2);
    gather2<<<(N_NODES*32 + 255)/256, 256>>>(out);
}

// round 11
// speedup vs baseline: 1.1758x; 1.1604x over previous
#include <cuda_runtime.h>
#include <cuda_bf16.h>
#include <cuda_fp16.h>
#include <cstdint>

#define N_NODES 10000
#define DIN 128
#define H1 8
#define F1 64
#define C1 512            // H1*F1
#define E0 80000
#define NE (2*E0 + N_NODES)   // 170000
#define F2 64
#define NEG_SLOPE 0.2f
#define FULL 0xffffffffu
#define NXP (N_NODES*(DIN/2))    // 640000

// ---------------- scratch (static device globals; no allocation) -------------
static __device__ int      g_src[NE];
static __device__ int      g_dst[NE];
static __device__ int      g_cnt[N_NODES];
static __device__ int      g_cursor[N_NODES];
static __device__ int      g_rowptr[N_NODES + 1];
static __device__ int      g_nbr[NE];              // CSR by dst: src indices
static __device__ uint32_t g_XH[NXP];              // x split, [n][kpair]
static __device__ uint32_t g_XL[NXP];
static __device__ uint32_t g_B1H[(DIN/2)*C1];      // W1 repacked+split, kpair-major
static __device__ uint32_t g_B1L[(DIN/2)*C1];
static __device__ __half2  g_P1h[N_NODES*(C1/2)];  // proj1 as fp16 pairs (gather feed)
static __device__ float    g_as1[N_NODES*H1];
static __device__ float    g_an1[N_NODES*H1];
static __device__ float    g_hbuf[N_NODES*C1];     // layer-1 output (post ELU), fp32
static __device__ float    g_p2part[4*N_NODES*F2]; // split-K partials for gemm2
static __device__ float    g_proj2[N_NODES*F2];
static __device__ float    g_as2[N_NODES];
static __device__ float    g_an2[N_NODES];

__device__ __forceinline__ void split_pack(float v0, float v1,
                                           uint32_t& hi, uint32_t& lo) {
    __nv_bfloat162 h2 = __floats2bfloat162_rn(v0, v1);
    float r0 = v0 - __low2float(h2);
    float r1 = v1 - __high2float(h2);
    __nv_bfloat162 l2 = __floats2bfloat162_rn(r0, r1);
    hi = *(const uint32_t*)&h2;
    lo = *(const uint32_t*)&l2;
}

// ---------------- prep A: edge decode + degree count (stream 2) --------------
__global__ void prep_edges(const int* __restrict__ e32) {
    int i = blockIdx.x * blockDim.x + threadIdx.x;
    if (i >= NE) return;
    bool is64 = (e32[1] == 0) && (e32[3] == 0) && (e32[5] == 0) && (e32[7] == 0);
    int s, d;
    if (i < NE - N_NODES) {
        int j  = (i < E0) ? i : (i - E0);
        int si = (i < E0) ? j : (E0 + j);
        int di = (i < E0) ? (E0 + j) : j;
        s = is64 ? e32[2*si] : e32[si];
        d = is64 ? e32[2*di] : e32[di];
    } else {
        s = i - (NE - N_NODES); d = s;
    }
    s = min(max(s, 0), N_NODES - 1);
    d = min(max(d, 0), N_NODES - 1);
    g_src[i] = s; g_dst[i] = d;
    atomicAdd(&g_cnt[d], 1);
}

// ---------------- prep B: x + W1 splits (main stream, feeds gemm1) -----------
__global__ void prep_splits(const float* __restrict__ W1,
                            const float* __restrict__ x) {
    int i = blockIdx.x * blockDim.x + threadIdx.x;
    if (i < NXP) {
        float2 v = *(const float2*)&x[2*i];
        split_pack(v.x, v.y, g_XH[i], g_XL[i]);
    }
    if (i < (DIN/2)*C1) {
        int kp = i / C1, c = i % C1;
        int h = c >> 6, f = c & 63;
        float v0 = W1[(h*DIN + 2*kp)*F1 + f];
        float v1 = W1[(h*DIN + 2*kp + 1)*F1 + f];
        split_pack(v0, v1, g_B1H[i], g_B1L[i]);
    }
}

// ---------------- exclusive scan of in-degrees (single block) ----------------
__global__ void scan_kernel() {
    __shared__ int ssum[1024];
    const int t = threadIdx.x;
    const int per = (N_NODES + 1023) / 1024;   // 10
    int base = t * per;
    int loc[16];
    int s = 0;
#pragma unroll
    for (int i = 0; i < per; i++) {
        int idx = base + i;
        int v = (idx < N_NODES) ? g_cnt[idx] : 0;
        loc[i] = v; s += v;
    }
    ssum[t] = s;
    __syncthreads();
    for (int off = 1; off < 1024; off <<= 1) {
        int v = (t >= off) ? ssum[t - off] : 0;
        __syncthreads();
        ssum[t] += v;
        __syncthreads();
    }
    int run = (t > 0) ? ssum[t - 1] : 0;
#pragma unroll
    for (int i = 0; i < per; i++) {
        int idx = base + i;
        if (idx < N_NODES) { g_rowptr[idx] = run; g_cursor[idx] = run; run += loc[i]; }
    }
    if (t == 1023) g_rowptr[N_NODES] = NE;
}

__global__ void fill_csr() {
    int e = blockIdx.x * blockDim.x + threadIdx.x;
    if (e >= NE) return;
    int d = g_dst[e];
    int slot = atomicAdd(&g_cursor[d], 1);   // cursor pre-seeded with rowptr
    g_nbr[slot] = g_src[e];
}

// ---------------- bf16x3 tensor-core MMA (m16n8k16) --------------------------
#define MMA_BF16(D, A0, A1, A2, A3, B0, B1) \
    asm("mma.sync.aligned.m16n8k16.row.col.f32.bf16.bf16.f32 " \
        "{%0,%1,%2,%3}, {%4,%5,%6,%7}, {%8,%9}, {%0,%1,%2,%3};" \
        : "+f"(D[0]), "+f"(D[1]), "+f"(D[2]), "+f"(D[3]) \
        : "r"(A0), "r"(A1), "r"(A2), "r"(A3), "r"(B0), "r"(B1))

// ---------------- GEMM1: 128x64 tile, pre-split A/B, fused alpha1 ------------
__global__ __launch_bounds__(256) void gemm1_kernel(const float* __restrict__ a1) {
    __shared__ uint32_t AsH[128][12], AsL[128][12];
    __shared__ uint32_t BsH[64][12],  BsL[64][12];
    __shared__ float sAs[64], sAn[64];
    __shared__ float salS[128][2], salN[128][2];

    const int tid = threadIdx.x;
    const int lane = tid & 31, wid = tid >> 5;
    const int wm = wid >> 1, wn = wid & 1;
    const int g = lane >> 2, tig = lane & 3;
    const int row0 = blockIdx.y * 128;
    const int h = blockIdx.x;
    const int col0 = h * 64;
    const int M = N_NODES;

    if (tid < 64) {
        sAs[tid] = __ldg(&a1[h*2*F1 + tid]);
        sAn[tid] = __ldg(&a1[h*2*F1 + F1 + tid]);
    }

    float acc[2][4][4];
#pragma unroll
    for (int mi = 0; mi < 2; mi++)
#pragma unroll
        for (int ni = 0; ni < 4; ni++)
#pragma unroll
            for (int q = 0; q < 4; q++) acc[mi][ni][q] = 0.f;

    for (int k0 = 0; k0 < DIN; k0 += 16) {
        const int kpb = k0 >> 1;
#pragma unroll
        for (int t = 0; t < 4; t++) {
            int idx = tid + t*256;
            int r = idx >> 3, kk = idx & 7;
            int grow = row0 + r;
            if (grow < M) {
                size_t gi = (size_t)grow*(DIN/2) + kpb + kk;
                AsH[r][kk] = g_XH[gi];
                AsL[r][kk] = g_XL[gi];
            } else {
                AsH[r][kk] = 0u; AsL[r][kk] = 0u;
            }
        }
#pragma unroll
        for (int t = 0; t < 2; t++) {
            int idx = tid + t*256;
            int kk = idx >> 6, c = idx & 63;
            size_t gi = (size_t)(kpb + kk)*C1 + col0 + c;
            BsH[c][kk] = g_B1H[gi];
            BsL[c][kk] = g_B1L[gi];
        }
        __syncthreads();

        uint32_t bh[4][2], bl[4][2];
#pragma unroll
        for (int ni = 0; ni < 4; ni++) {
            int c = wn*32 + ni*8 + g;
            bh[ni][0] = BsH[c][tig];     bh[ni][1] = BsH[c][tig + 4];
            bl[ni][0] = BsL[c][tig];     bl[ni][1] = BsL[c][tig + 4];
        }
#pragma unroll
        for (int mi = 0; mi < 2; mi++) {
            int r = wm*32 + mi*16 + g;
            uint32_t ah0 = AsH[r][tig],     ah1 = AsH[r + 8][tig];
            uint32_t ah2 = AsH[r][tig + 4], ah3 = AsH[r + 8][tig + 4];
            uint32_t al0 = AsL[r][tig],     al1 = AsL[r + 8][tig];
            uint32_t al2 = AsL[r][tig + 4], al3 = AsL[r + 8][tig + 4];
#pragma unroll
            for (int ni = 0; ni < 4; ni++) {
                MMA_BF16(acc[mi][ni], ah0, ah1, ah2, ah3, bh[ni][0], bh[ni][1]);
                MMA_BF16(acc[mi][ni], ah0, ah1, ah2, ah3, bl[ni][0], bl[ni][1]);
                MMA_BF16(acc[mi][ni], al0, al1, al2, al3, bh[ni][0], bh[ni][1]);
            }
        }
        __syncthreads();
    }

    // epilogue: fp16 proj1 store + fused alpha1 (fp32)
#pragma unroll
    for (int mi = 0; mi < 2; mi++) {
        float s0 = 0.f, s8 = 0.f, n0 = 0.f, n8 = 0.f;
        int growA = row0 + wm*32 + mi*16 + g;
        int growB = growA + 8;
#pragma unroll
        for (int ni = 0; ni < 4; ni++) {
            float c0 = acc[mi][ni][0], c1 = acc[mi][ni][1];
            float c2 = acc[mi][ni][2], c3 = acc[mi][ni][3];
            int cl = wn*32 + ni*8 + 2*tig;
            size_t cp = (size_t)(col0 + cl) >> 1;
            if (growA < M)
                g_P1h[(size_t)growA*(C1/2) + cp] = __floats2half2_rn(c0, c1);
            if (growB < M)
                g_P1h[(size_t)growB*(C1/2) + cp] = __floats2half2_rn(c2, c3);
            float as0 = sAs[cl], as1 = sAs[cl + 1];
            float an0 = sAn[cl], an1 = sAn[cl + 1];
            s0 += c0*as0 + c1*as1;  n0 += c0*an0 + c1*an1;
            s8 += c2*as0 + c3*as1;  n8 += c2*an0 + c3*an1;
        }
#pragma unroll
        for (int o = 1; o <= 2; o <<= 1) {
            s0 += __shfl_xor_sync(FULL, s0, o);
            s8 += __shfl_xor_sync(FULL, s8, o);
            n0 += __shfl_xor_sync(FULL, n0, o);
            n8 += __shfl_xor_sync(FULL, n8, o);
        }
        if (tig == 0) {
            int rl = wm*32 + mi*16 + g;
            salS[rl][wn] = s0;  salN[rl][wn] = n0;
            salS[rl + 8][wn] = s8;  salN[rl + 8][wn] = n8;
        }
    }
    __syncthreads();
    if (tid < 128) {
        int grow = row0 + tid;
        if (grow < M) {
            g_as1[grow*H1 + h] = salS[tid][0] + salS[tid][1];
            g_an1[grow*H1 + h] = salN[tid][0] + salN[tid][1];
        }
    }
}

// ---------------- GEMM2 split-K SIMT: 64x64 tile, K-chunk 128 per z ----------
__global__ void gemm2_kernel(const float* __restrict__ B) {
    __shared__ __align__(16) float As[16][68];
    __shared__ __align__(16) float Bs[16][64];
    const float* A = g_hbuf;
    const int M = N_NODES, N = F2, K = C1;
    const int tid = threadIdx.x;
    const int tx = tid & 15, ty = tid >> 4;
    const int row0 = blockIdx.y * 64;
    const int kz0 = blockIdx.z * (K/4);
    float* C = g_p2part + (size_t)blockIdx.z * N_NODES * F2;
    float acc[4][4];
#pragma unroll
    for (int i = 0; i < 4; i++)
#pragma unroll
        for (int j = 0; j < 4; j++) acc[i][j] = 0.f;

    for (int k0 = kz0; k0 < kz0 + K/4; k0 += 16) {
#pragma unroll
        for (int l = 0; l < 4; l++) {
            int i = tid + l*256;
            int r = i >> 4, kk = i & 15;
            int gr = row0 + r;
            As[kk][r] = (gr < M) ? A[(size_t)gr*K + k0 + kk] : 0.f;
        }
        {
            int kk = tid >> 6, c = tid & 63;
            Bs[kk][c]      = B[(size_t)(k0 + kk)*N + c];
            Bs[kk + 4][c]  = B[(size_t)(k0 + kk + 4)*N + c];
            Bs[kk + 8][c]  = B[(size_t)(k0 + kk + 8)*N + c];
            Bs[kk + 12][c] = B[(size_t)(k0 + kk + 12)*N + c];
        }
        __syncthreads();
#pragma unroll
        for (int kk = 0; kk < 16; kk++) {
            float4 av = *(const float4*)&As[kk][ty*4];
            float4 bv = *(const float4*)&Bs[kk][tx*4];
            float a[4] = {av.x, av.y, av.z, av.w};
            float b[4] = {bv.x, bv.y, bv.z, bv.w};
#pragma unroll
            for (int i = 0; i < 4; i++)
#pragma unroll
                for (int j = 0; j < 4; j++) acc[i][j] += a[i]*b[j];
        }
        __syncthreads();
    }
#pragma unroll
    for (int i = 0; i < 4; i++) {
        int gr = row0 + ty*4 + i;
        if (gr < M) {
            *(float4*)&C[(size_t)gr*N + tx*4] =
                make_float4(acc[i][0], acc[i][1], acc[i][2], acc[i][3]);
        }
    }
}

// ---------------- combine split-K partials + attention (layer 2) -------------
__global__ void alpha2_combine(const float* __restrict__ a2) {
    int t = blockIdx.x * blockDim.x + threadIdx.x;
    int w = t >> 5, lane = t & 31;
    if (w >= N_NODES) return;
    const size_t NF = (size_t)N_NODES * F2;
    size_t base = (size_t)w*F2;
    float v0 = g_p2part[base + lane]        + g_p2part[NF + base + lane]
             + g_p2part[2*NF + base + lane] + g_p2part[3*NF + base + lane];
    float v1 = g_p2part[base + lane + 32]        + g_p2part[NF + base + lane + 32]
             + g_p2part[2*NF + base + lane + 32] + g_p2part[3*NF + base + lane + 32];
    g_proj2[base + lane] = v0;
    g_proj2[base + lane + 32] = v1;
    float s  = v0*a2[lane]      + v1*a2[lane + 32];
    float tn = v0*a2[F2 + lane] + v1*a2[F2 + lane + 32];
#pragma unroll
    for (int o = 16; o; o >>= 1) {
        s  += __shfl_xor_sync(FULL, s, o);
        tn += __shfl_xor_sync(FULL, tn, o);
    }
    if (!lane) { g_as2[w] = s; g_an2[w] = tn; }
}

// ---------------- fused gather1: single-pass softmax (no max shift) ----------
// Softmax is shift-invariant; logits |v| <~ 8 so exp is fp32-safe without it.
__global__ void gather1() {
    int t = blockIdx.x * blockDim.x + threadIdx.x;
    int w = t >> 5, lane = t & 31;
    if (w >= N_NODES*H1) return;
    int n = w >> 3, h = w & 7;
    int beg = g_rowptr[n], end = g_rowptr[n + 1];
    float as = g_as1[n*H1 + h];

    const int half = lane >> 4;
    const int fl2 = (lane & 15) * 2;            // half2 offset within head slice
    const __half2* projh = g_P1h + h*(F1/2) + fl2;
    float a0 = 0.f, a1v = 0.f, a2v = 0.f, a3 = 0.f, den = 0.f;
    for (int base = beg; base < end; base += 32) {
        int i = base + lane;
        int s = 0; float wgt = 0.f;
        if (i < end) {
            s = g_nbr[i];
            float v = as + g_an1[s*H1 + h];
            v = (v >= 0.f) ? v : NEG_SLOPE*v;
            wgt = __expf(v);
            den += wgt;
        }
        int cnt = min(32, end - base);
        if (cnt == 32) {
#pragma unroll
            for (int j = 0; j < 16; j++) {
                int sl = 2*j + half;
                float ww = __shfl_sync(FULL, wgt, sl);
                int ss = __shfl_sync(FULL, s, sl);
                uint2 u = *(const uint2*)&projh[(size_t)ss*(C1/2)];
                float2 f0 = __half22float2(*reinterpret_cast<__half2*>(&u.x));
                float2 f1 = __half22float2(*reinterpret_cast<__half2*>(&u.y));
                a0 += ww*f0.x; a1v += ww*f0.y; a2v += ww*f1.x; a3 += ww*f1.y;
            }
        } else {
            int jmax = (cnt + 1) >> 1;
            for (int j = 0; j < jmax; j++) {
                int sl = 2*j + half;
                float ww = __shfl_sync(FULL, wgt, sl);
                int ss = __shfl_sync(FULL, s, sl);
                uint2 u = *(const uint2*)&projh[(size_t)ss*(C1/2)];
                float2 f0 = __half22float2(*reinterpret_cast<__half2*>(&u.x));
                float2 f1 = __half22float2(*reinterpret_cast<__half2*>(&u.y));
                a0 += ww*f0.x; a1v += ww*f0.y; a2v += ww*f1.x; a3 += ww*f1.y;
            }
        }
    }
    a0  += __shfl_xor_sync(FULL, a0, 16);
    a1v += __shfl_xor_sync(FULL, a1v, 16);
    a2v += __shfl_xor_sync(FULL, a2v, 16);
    a3  += __shfl_xor_sync(FULL, a3, 16);
#pragma unroll
    for (int o = 16; o; o >>= 1) den += __shfl_xor_sync(FULL, den, o);
    if (lane < 16) {
        float inv = 1.f / den;
        a0 *= inv; a1v *= inv; a2v *= inv; a3 *= inv;
        a0  = (a0  > 0.f) ? a0  : expm1f(a0);
        a1v = (a1v > 0.f) ? a1v : expm1f(a1v);
        a2v = (a2v > 0.f) ? a2v : expm1f(a2v);
        a3  = (a3  > 0.f) ? a3  : expm1f(a3);
        *(float4*)&g_hbuf[(size_t)n*C1 + h*F1 + fl2*2] = make_float4(a0, a1v, a2v, a3);
    }
}

// ---------------- fused gather layer 2 (single-pass, fp32 features) ----------
__global__ void gather2(float* __restrict__ out) {
    int t = blockIdx.x * blockDim.x + threadIdx.x;
    int w = t >> 5, lane = t & 31;
    if (w >= N_NODES) return;
    int n = w;
    int beg = g_rowptr[n], end = g_rowptr[n + 1];
    float as = g_as2[n];

    const int half = lane >> 4;
    const int fl = (lane & 15) * 4;
    const float* projl = g_proj2 + fl;
    float a0 = 0.f, a1v = 0.f, a2v = 0.f, a3 = 0.f, den = 0.f;
    for (int base = beg; base < end; base += 32) {
        int i = base + lane;
        int s = 0; float wgt = 0.f;
        if (i < end) {
            s = g_nbr[i];
            float v = as + g_an2[s];
            v = (v >= 0.f) ? v : NEG_SLOPE*v;
            wgt = __expf(v);
            den += wgt;
        }
        int cnt = min(32, end - base);
        if (cnt == 32) {
#pragma unroll
            for (int j = 0; j < 16; j++) {
                int sl = 2*j + half;
                float ww = __shfl_sync(FULL, wgt, sl);
                int ss = __shfl_sync(FULL, s, sl);
                float4 p = *(const float4*)&projl[(size_t)ss*F2];
                a0 += ww*p.x; a1v += ww*p.y; a2v += ww*p.z; a3 += ww*p.w;
            }
        } else {
            int jmax = (cnt + 1) >> 1;
            for (int j = 0; j < jmax; j++) {
                int sl = 2*j + half;
                float ww = __shfl_sync(FULL, wgt, sl);
                int ss = __shfl_sync(FULL, s, sl);
                float4 p = *(const float4*)&projl[(size_t)ss*F2];
                a0 += ww*p.x; a1v += ww*p.y; a2v += ww*p.z; a3 += ww*p.w;
            }
        }
    }
    a0  += __shfl_xor_sync(FULL, a0, 16);
    a1v += __shfl_xor_sync(FULL, a1v, 16);
    a2v += __shfl_xor_sync(FULL, a2v, 16);
    a3  += __shfl_xor_sync(FULL, a3, 16);
#pragma unroll
    for (int o = 16; o; o >>= 1) den += __shfl_xor_sync(FULL, den, o);
    if (lane < 16) {
        float inv = 1.f / den;
        *(float4*)&out[(size_t)n*F2 + fl] =
            make_float4(a0*inv, a1v*inv, a2v*inv, a3*inv);
    }
}

// ---------------- launch -------------------------------------------------------
extern "C" void kernel_launch(void* const* d_in, const int* in_sizes, int n_in,
                              void* d_out, int out_size) {
    const float* x     = (const float*)d_in[0];
    const int*   edges = (const int*)d_in[1];
    const float* W1    = (const float*)d_in[2];
    const float* a1    = (const float*)d_in[3];
    const float* W2    = (const float*)d_in[4];
    const float* a2    = (const float*)d_in[5];
    float* out = (float*)d_out;

    static cudaStream_t s2 = nullptr;
    static cudaEvent_t evFork = nullptr, evCSR = nullptr;
    if (s2 == nullptr) {
        cudaStreamCreateWithFlags(&s2, cudaStreamNonBlocking);
        cudaEventCreateWithFlags(&evFork, cudaEventDisableTiming);
        cudaEventCreateWithFlags(&evCSR, cudaEventDisableTiming);
    }

    void* cnt_ptr = nullptr;
    cudaGetSymbolAddress(&cnt_ptr, g_cnt);

    // fork: CSR build on s2, concurrent with split+gemm1 on main stream
    cudaEventRecord(evFork, 0);
    cudaStreamWaitEvent(s2, evFork, 0);

    cudaMemsetAsync(cnt_ptr, 0, N_NODES*sizeof(int), s2);
    prep_edges<<<(NE + 255)/256, 256, 0, s2>>>(edges);
    scan_kernel<<<1, 1024, 0, s2>>>();
    fill_csr<<<(NE + 255)/256, 256, 0, s2>>>();
    cudaEventRecord(evCSR, s2);

    prep_splits<<<(NXP + 255)/256, 256>>>(W1, x);
    gemm1_kernel<<<dim3(H1, (N_NODES + 127)/128), 256>>>(a1);

    // join: gather1 needs CSR + gemm1
    cudaStreamWaitEvent(0, evCSR, 0);
    gather1<<<(N_NODES*H1*32 + 255)/256, 256>>>();

    // layer 2
    gemm2_kernel<<<dim3(1, (N_NODES + 63)/64, 4), 256>>>(W2);
    alpha2_combine<<<(N_NODES*32 + 255)/256, 256>>>(a2);
    gather2<<<(N_NODES*32 + 255)/256, 256>>>(out);
}

// round 12
// speedup vs baseline: 1.1789x; 1.0027x over previous
#include <cuda_runtime.h>
#include <cuda_bf16.h>
#include <cuda_fp16.h>
#include <cstdint>

#define N_NODES 10000
#define DIN 128
#define H1 8
#define F1 64
#define C1 512            // H1*F1
#define E0 80000
#define NE (2*E0 + N_NODES)   // 170000
#define F2 64
#define NEG_SLOPE 0.2f
#define FULL 0xffffffffu
#define NXP (N_NODES*(DIN/2))    // 640000
#define SPLITK 8

// ---------------- scratch (static device globals; no allocation) -------------
static __device__ int      g_src[NE];
static __device__ int      g_dst[NE];
static __device__ int      g_cnt[N_NODES];
static __device__ int      g_cursor[N_NODES];
static __device__ int      g_rowptr[N_NODES + 1];
static __device__ int      g_nbr[NE];              // CSR by dst: src indices
static __device__ uint32_t g_XH[NXP];              // x split, [n][kpair]
static __device__ uint32_t g_XL[NXP];
static __device__ uint32_t g_B1H[(DIN/2)*C1];      // W1 repacked+split, kpair-major
static __device__ uint32_t g_B1L[(DIN/2)*C1];
static __device__ __half2  g_P1h[N_NODES*(C1/2)];  // proj1 as fp16 pairs (gather feed)
static __device__ float    g_as1[N_NODES*H1];
static __device__ float    g_an1[N_NODES*H1];
static __device__ float    g_hbuf[N_NODES*C1];     // layer-1 output (post ELU), fp32
static __device__ float    g_p2part[SPLITK*N_NODES*F2]; // split-K partials for gemm2
static __device__ float    g_proj2[N_NODES*F2];
static __device__ float    g_as2[N_NODES];
static __device__ float    g_an2[N_NODES];

__device__ __forceinline__ void split_pack(float v0, float v1,
                                           uint32_t& hi, uint32_t& lo) {
    __nv_bfloat162 h2 = __floats2bfloat162_rn(v0, v1);
    float r0 = v0 - __low2float(h2);
    float r1 = v1 - __high2float(h2);
    __nv_bfloat162 l2 = __floats2bfloat162_rn(r0, r1);
    hi = *(const uint32_t*)&h2;
    lo = *(const uint32_t*)&l2;
}

// ---------------- prep A: edge decode + degree count (stream 2) --------------
__global__ void prep_edges(const int* __restrict__ e32) {
    int i = blockIdx.x * blockDim.x + threadIdx.x;
    if (i >= NE) return;
    bool is64 = (e32[1] == 0) && (e32[3] == 0) && (e32[5] == 0) && (e32[7] == 0);
    int s, d;
    if (i < NE - N_NODES) {
        int j  = (i < E0) ? i : (i - E0);
        int si = (i < E0) ? j : (E0 + j);
        int di = (i < E0) ? (E0 + j) : j;
        s = is64 ? e32[2*si] : e32[si];
        d = is64 ? e32[2*di] : e32[di];
    } else {
        s = i - (NE - N_NODES); d = s;
    }
    s = min(max(s, 0), N_NODES - 1);
    d = min(max(d, 0), N_NODES - 1);
    g_src[i] = s; g_dst[i] = d;
    atomicAdd(&g_cnt[d], 1);
}

// ---------------- prep B: x + W1 splits (main stream, feeds gemm1) -----------
__global__ void prep_splits(const float* __restrict__ W1,
                            const float* __restrict__ x) {
    int i = blockIdx.x * blockDim.x + threadIdx.x;
    if (i < NXP) {
        float2 v = *(const float2*)&x[2*i];
        split_pack(v.x, v.y, g_XH[i], g_XL[i]);
    }
    if (i < (DIN/2)*C1) {
        int kp = i / C1, c = i % C1;
        int h = c >> 6, f = c & 63;
        float v0 = W1[(h*DIN + 2*kp)*F1 + f];
        float v1 = W1[(h*DIN + 2*kp + 1)*F1 + f];
        split_pack(v0, v1, g_B1H[i], g_B1L[i]);
    }
}

// ---------------- exclusive scan of in-degrees (single block) ----------------
__global__ void scan_kernel() {
    __shared__ int ssum[1024];
    const int t = threadIdx.x;
    const int per = (N_NODES + 1023) / 1024;   // 10
    int base = t * per;
    int loc[16];
    int s = 0;
#pragma unroll
    for (int i = 0; i < per; i++) {
        int idx = base + i;
        int v = (idx < N_NODES) ? g_cnt[idx] : 0;
        loc[i] = v; s += v;
    }
    ssum[t] = s;
    __syncthreads();
    for (int off = 1; off < 1024; off <<= 1) {
        int v = (t >= off) ? ssum[t - off] : 0;
        __syncthreads();
        ssum[t] += v;
        __syncthreads();
    }
    int run = (t > 0) ? ssum[t - 1] : 0;
#pragma unroll
    for (int i = 0; i < per; i++) {
        int idx = base + i;
        if (idx < N_NODES) { g_rowptr[idx] = run; g_cursor[idx] = run; run += loc[i]; }
    }
    if (t == 1023) g_rowptr[N_NODES] = NE;
}

__global__ void fill_csr() {
    int e = blockIdx.x * blockDim.x + threadIdx.x;
    if (e >= NE) return;
    int d = g_dst[e];
    int slot = atomicAdd(&g_cursor[d], 1);   // cursor pre-seeded with rowptr
    g_nbr[slot] = g_src[e];
}

// ---------------- bf16x3 tensor-core MMA (m16n8k16) --------------------------
#define MMA_BF16(D, A0, A1, A2, A3, B0, B1) \
    asm("mma.sync.aligned.m16n8k16.row.col.f32.bf16.bf16.f32 " \
        "{%0,%1,%2,%3}, {%4,%5,%6,%7}, {%8,%9}, {%0,%1,%2,%3};" \
        : "+f"(D[0]), "+f"(D[1]), "+f"(D[2]), "+f"(D[3]) \
        : "r"(A0), "r"(A1), "r"(A2), "r"(A3), "r"(B0), "r"(B1))

// ---------------- GEMM1: 128x64 tile, double-buffered, fused alpha1 ----------
__global__ __launch_bounds__(256) void gemm1_kernel(const float* __restrict__ a1) {
    __shared__ uint32_t AsH[2][128][12], AsL[2][128][12];
    __shared__ uint32_t BsH[2][64][12],  BsL[2][64][12];
    __shared__ float sAs[64], sAn[64];
    __shared__ float salS[128][2], salN[128][2];

    const int tid = threadIdx.x;
    const int lane = tid & 31, wid = tid >> 5;
    const int wm = wid >> 1, wn = wid & 1;
    const int g = lane >> 2, tig = lane & 3;
    const int row0 = blockIdx.y * 128;
    const int h = blockIdx.x;
    const int col0 = h * 64;
    const int M = N_NODES;

    if (tid < 64) {
        sAs[tid] = __ldg(&a1[h*2*F1 + tid]);
        sAn[tid] = __ldg(&a1[h*2*F1 + F1 + tid]);
    }

    // per-thread load coordinates (constant)
    const int ar = tid >> 3, akk = tid & 7;            // A: 2 rows/thread (ar, ar+? no: 4 t-iters)
    const int bkk = tid >> 6, bc = tid & 63;           // B: 2 k-rows/thread

    float acc[2][4][4];
#pragma unroll
    for (int mi = 0; mi < 2; mi++)
#pragma unroll
        for (int ni = 0; ni < 4; ni++)
#pragma unroll
            for (int q = 0; q < 4; q++) acc[mi][ni][q] = 0.f;

    // preload tile 0 into buffer 0
#pragma unroll
    for (int t = 0; t < 4; t++) {
        int idx = tid + t*256;
        int r = idx >> 3, kk = idx & 7;
        int grow = row0 + r;
        if (grow < M) {
            size_t gi = (size_t)grow*(DIN/2) + kk;
            AsH[0][r][kk] = g_XH[gi];
            AsL[0][r][kk] = g_XL[gi];
        } else { AsH[0][r][kk] = 0u; AsL[0][r][kk] = 0u; }
    }
#pragma unroll
    for (int t = 0; t < 2; t++) {
        int idx = tid + t*256;
        int kk = idx >> 6, c = idx & 63;
        size_t gi = (size_t)kk*C1 + col0 + c;
        BsH[0][c][kk] = g_B1H[gi];
        BsL[0][c][kk] = g_B1L[gi];
    }
    __syncthreads();

    const int nIter = DIN / 16;    // 8
    int p = 0;
    for (int it = 0; it < nIter; it++) {
        // prefetch next tile into registers
        uint32_t paH[4], paL[4], pbH[2], pbL[2];
        if (it + 1 < nIter) {
            const int kpb = (it + 1) * 8;
#pragma unroll
            for (int t = 0; t < 4; t++) {
                int idx = tid + t*256;
                int r = idx >> 3, kk = idx & 7;
                int grow = row0 + r;
                if (grow < M) {
                    size_t gi = (size_t)grow*(DIN/2) + kpb + kk;
                    paH[t] = g_XH[gi]; paL[t] = g_XL[gi];
                } else { paH[t] = 0u; paL[t] = 0u; }
            }
#pragma unroll
            for (int t = 0; t < 2; t++) {
                int idx = tid + t*256;
                int kk = idx >> 6, c = idx & 63;
                size_t gi = (size_t)(kpb + kk)*C1 + col0 + c;
                pbH[t] = g_B1H[gi]; pbL[t] = g_B1L[gi];
            }
        }

        // MMAs on buffer p
        uint32_t bh[4][2], bl[4][2];
#pragma unroll
        for (int ni = 0; ni < 4; ni++) {
            int c = wn*32 + ni*8 + g;
            bh[ni][0] = BsH[p][c][tig];     bh[ni][1] = BsH[p][c][tig + 4];
            bl[ni][0] = BsL[p][c][tig];     bl[ni][1] = BsL[p][c][tig + 4];
        }
#pragma unroll
        for (int mi = 0; mi < 2; mi++) {
            int r = wm*32 + mi*16 + g;
            uint32_t ah0 = AsH[p][r][tig],     ah1 = AsH[p][r + 8][tig];
            uint32_t ah2 = AsH[p][r][tig + 4], ah3 = AsH[p][r + 8][tig + 4];
            uint32_t al0 = AsL[p][r][tig],     al1 = AsL[p][r + 8][tig];
            uint32_t al2 = AsL[p][r][tig + 4], al3 = AsL[p][r + 8][tig + 4];
#pragma unroll
            for (int ni = 0; ni < 4; ni++) {
                MMA_BF16(acc[mi][ni], ah0, ah1, ah2, ah3, bh[ni][0], bh[ni][1]);
                MMA_BF16(acc[mi][ni], ah0, ah1, ah2, ah3, bl[ni][0], bl[ni][1]);
                MMA_BF16(acc[mi][ni], al0, al1, al2, al3, bh[ni][0], bh[ni][1]);
            }
        }

        // commit prefetch into other buffer
        if (it + 1 < nIter) {
            int q = p ^ 1;
#pragma unroll
            for (int t = 0; t < 4; t++) {
                int idx = tid + t*256;
                int r = idx >> 3, kk = idx & 7;
                AsH[q][r][kk] = paH[t];
                AsL[q][r][kk] = paL[t];
            }
#pragma unroll
            for (int t = 0; t < 2; t++) {
                int idx = tid + t*256;
                int kk = idx >> 6, c = idx & 63;
                BsH[q][c][kk] = pbH[t];
                BsL[q][c][kk] = pbL[t];
            }
            __syncthreads();
            p = q;
        }
    }

    // epilogue: fp16 proj1 store + fused alpha1 (fp32)
#pragma unroll
    for (int mi = 0; mi < 2; mi++) {
        float s0 = 0.f, s8 = 0.f, n0 = 0.f, n8 = 0.f;
        int growA = row0 + wm*32 + mi*16 + g;
        int growB = growA + 8;
#pragma unroll
        for (int ni = 0; ni < 4; ni++) {
            float c0 = acc[mi][ni][0], c1 = acc[mi][ni][1];
            float c2 = acc[mi][ni][2], c3 = acc[mi][ni][3];
            int cl = wn*32 + ni*8 + 2*tig;
            size_t cp = (size_t)(col0 + cl) >> 1;
            if (growA < M)
                g_P1h[(size_t)growA*(C1/2) + cp] = __floats2half2_rn(c0, c1);
            if (growB < M)
                g_P1h[(size_t)growB*(C1/2) + cp] = __floats2half2_rn(c2, c3);
            float as0 = sAs[cl], as1 = sAs[cl + 1];
            float an0 = sAn[cl], an1 = sAn[cl + 1];
            s0 += c0*as0 + c1*as1;  n0 += c0*an0 + c1*an1;
            s8 += c2*as0 + c3*as1;  n8 += c2*an0 + c3*an1;
        }
#pragma unroll
        for (int o = 1; o <= 2; o <<= 1) {
            s0 += __shfl_xor_sync(FULL, s0, o);
            s8 += __shfl_xor_sync(FULL, s8, o);
            n0 += __shfl_xor_sync(FULL, n0, o);
            n8 += __shfl_xor_sync(FULL, n8, o);
        }
        if (tig == 0) {
            int rl = wm*32 + mi*16 + g;
            salS[rl][wn] = s0;  salN[rl][wn] = n0;
            salS[rl + 8][wn] = s8;  salN[rl + 8][wn] = n8;
        }
    }
    __syncthreads();
    if (tid < 128) {
        int grow = row0 + tid;
        if (grow < M) {
            g_as1[grow*H1 + h] = salS[tid][0] + salS[tid][1];
            g_an1[grow*H1 + h] = salN[tid][0] + salN[tid][1];
        }
    }
}

// ---------------- GEMM2 split-K SIMT: 64x64 tile, K-chunk 64 per z -----------
__global__ void gemm2_kernel(const float* __restrict__ B) {
    __shared__ __align__(16) float As[16][68];
    __shared__ __align__(16) float Bs[16][64];
    const float* A = g_hbuf;
    const int M = N_NODES, N = F2, K = C1;
    const int tid = threadIdx.x;
    const int tx = tid & 15, ty = tid >> 4;
    const int row0 = blockIdx.y * 64;
    const int kz0 = blockIdx.z * (K/SPLITK);
    float* C = g_p2part + (size_t)blockIdx.z * N_NODES * F2;
    float acc[4][4];
#pragma unroll
    for (int i = 0; i < 4; i++)
#pragma unroll
        for (int j = 0; j < 4; j++) acc[i][j] = 0.f;

    for (int k0 = kz0; k0 < kz0 + K/SPLITK; k0 += 16) {
#pragma unroll
        for (int l = 0; l < 4; l++) {
            int i = tid + l*256;
            int r = i >> 4, kk = i & 15;
            int gr = row0 + r;
            As[kk][r] = (gr < M) ? A[(size_t)gr*K + k0 + kk] : 0.f;
        }
        {
            int kk = tid >> 6, c = tid & 63;
            Bs[kk][c]      = B[(size_t)(k0 + kk)*N + c];
            Bs[kk + 4][c]  = B[(size_t)(k0 + kk + 4)*N + c];
            Bs[kk + 8][c]  = B[(size_t)(k0 + kk + 8)*N + c];
            Bs[kk + 12][c] = B[(size_t)(k0 + kk + 12)*N + c];
        }
        __syncthreads();
#pragma unroll
        for (int kk = 0; kk < 16; kk++) {
            float4 av = *(const float4*)&As[kk][ty*4];
            float4 bv = *(const float4*)&Bs[kk][tx*4];
            float a[4] = {av.x, av.y, av.z, av.w};
            float b[4] = {bv.x, bv.y, bv.z, bv.w};
#pragma unroll
            for (int i = 0; i < 4; i++)
#pragma unroll
                for (int j = 0; j < 4; j++) acc[i][j] += a[i]*b[j];
        }
        __syncthreads();
    }
#pragma unroll
    for (int i = 0; i < 4; i++) {
        int gr = row0 + ty*4 + i;
        if (gr < M) {
            *(float4*)&C[(size_t)gr*N + tx*4] =
                make_float4(acc[i][0], acc[i][1], acc[i][2], acc[i][3]);
        }
    }
}

// ---------------- combine split-K partials + attention (layer 2) -------------
__global__ void alpha2_combine(const float* __restrict__ a2) {
    int t = blockIdx.x * blockDim.x + threadIdx.x;
    int w = t >> 5, lane = t & 31;
    if (w >= N_NODES) return;
    const size_t NF = (size_t)N_NODES * F2;
    size_t base = (size_t)w*F2;
    float v0 = 0.f, v1 = 0.f;
#pragma unroll
    for (int z = 0; z < SPLITK; z++) {
        v0 += g_p2part[z*NF + base + lane];
        v1 += g_p2part[z*NF + base + lane + 32];
    }
    g_proj2[base + lane] = v0;
    g_proj2[base + lane + 32] = v1;
    float s  = v0*a2[lane]      + v1*a2[lane + 32];
    float tn = v0*a2[F2 + lane] + v1*a2[F2 + lane + 32];
#pragma unroll
    for (int o = 16; o; o >>= 1) {
        s  += __shfl_xor_sync(FULL, s, o);
        tn += __shfl_xor_sync(FULL, tn, o);
    }
    if (!lane) { g_as2[w] = s; g_an2[w] = tn; }
}

// ---------------- fused gather1: single-pass softmax (no max shift) ----------
__global__ void gather1() {
    int t = blockIdx.x * blockDim.x + threadIdx.x;
    int w = t >> 5, lane = t & 31;
    if (w >= N_NODES*H1) return;
    int n = w >> 3, h = w & 7;
    int beg = g_rowptr[n], end = g_rowptr[n + 1];
    float as = g_as1[n*H1 + h];

    const int half = lane >> 4;
    const int fl2 = (lane & 15) * 2;
    const __half2* projh = g_P1h + h*(F1/2) + fl2;
    float a0 = 0.f, a1v = 0.f, a2v = 0.f, a3 = 0.f, den = 0.f;
    for (int base = beg; base < end; base += 32) {
        int i = base + lane;
        int s = 0; float wgt = 0.f;
        if (i < end) {
            s = g_nbr[i];
            float v = as + g_an1[s*H1 + h];
            v = (v >= 0.f) ? v : NEG_SLOPE*v;
            wgt = __expf(v);
            den += wgt;
        }
        int cnt = min(32, end - base);
        if (cnt == 32) {
#pragma unroll
            for (int j = 0; j < 16; j++) {
                int sl = 2*j + half;
                float ww = __shfl_sync(FULL, wgt, sl);
                int ss = __shfl_sync(FULL, s, sl);
                uint2 u = *(const uint2*)&projh[(size_t)ss*(C1/2)];
                float2 f0 = __half22float2(*reinterpret_cast<__half2*>(&u.x));
                float2 f1 = __half22float2(*reinterpret_cast<__half2*>(&u.y));
                a0 += ww*f0.x; a1v += ww*f0.y; a2v += ww*f1.x; a3 += ww*f1.y;
            }
        } else {
            int jmax = (cnt + 1) >> 1;
            for (int j = 0; j < jmax; j++) {
                int sl = 2*j + half;
                float ww = __shfl_sync(FULL, wgt, sl);
                int ss = __shfl_sync(FULL, s, sl);
                uint2 u = *(const uint2*)&projh[(size_t)ss*(C1/2)];
                float2 f0 = __half22float2(*reinterpret_cast<__half2*>(&u.x));
                float2 f1 = __half22float2(*reinterpret_cast<__half2*>(&u.y));
                a0 += ww*f0.x; a1v += ww*f0.y; a2v += ww*f1.x; a3 += ww*f1.y;
            }
        }
    }
    a0  += __shfl_xor_sync(FULL, a0, 16);
    a1v += __shfl_xor_sync(FULL, a1v, 16);
    a2v += __shfl_xor_sync(FULL, a2v, 16);
    a3  += __shfl_xor_sync(FULL, a3, 16);
#pragma unroll
    for (int o = 16; o; o >>= 1) den += __shfl_xor_sync(FULL, den, o);
    if (lane < 16) {
        float inv = 1.f / den;
        a0 *= inv; a1v *= inv; a2v *= inv; a3 *= inv;
        a0  = (a0  > 0.f) ? a0  : expm1f(a0);
        a1v = (a1v > 0.f) ? a1v : expm1f(a1v);
        a2v = (a2v > 0.f) ? a2v : expm1f(a2v);
        a3  = (a3  > 0.f) ? a3  : expm1f(a3);
        *(float4*)&g_hbuf[(size_t)n*C1 + h*F1 + fl2*2] = make_float4(a0, a1v, a2v, a3);
    }
}

// ---------------- fused gather layer 2 (single-pass, fp32 features) ----------
__global__ void gather2(float* __restrict__ out) {
    int t = blockIdx.x * blockDim.x + threadIdx.x;
    int w = t >> 5, lane = t & 31;
    if (w >= N_NODES) return;
    int n = w;
    int beg = g_rowptr[n], end = g_rowptr[n + 1];
    float as = g_as2[n];

    const int half = lane >> 4;
    const int fl = (lane & 15) * 4;
    const float* projl = g_proj2 + fl;
    float a0 = 0.f, a1v = 0.f, a2v = 0.f, a3 = 0.f, den = 0.f;
    for (int base = beg; base < end; base += 32) {
        int i = base + lane;
        int s = 0; float wgt = 0.f;
        if (i < end) {
            s = g_nbr[i];
            float v = as + g_an2[s];
            v = (v >= 0.f) ? v : NEG_SLOPE*v;
            wgt = __expf(v);
            den += wgt;
        }
        int cnt = min(32, end - base);
        if (cnt == 32) {
#pragma unroll
            for (int j = 0; j < 16; j++) {
                int sl = 2*j + half;
                float ww = __shfl_sync(FULL, wgt, sl);
                int ss = __shfl_sync(FULL, s, sl);
                float4 p = *(const float4*)&projl[(size_t)ss*F2];
                a0 += ww*p.x; a1v += ww*p.y; a2v += ww*p.z; a3 += ww*p.w;
            }
        } else {
            int jmax = (cnt + 1) >> 1;
            for (int j = 0; j < jmax; j++) {
                int sl = 2*j + half;
                float ww = __shfl_sync(FULL, wgt, sl);
                int ss = __shfl_sync(FULL, s, sl);
                float4 p = *(const float4*)&projl[(size_t)ss*F2];
                a0 += ww*p.x; a1v += ww*p.y; a2v += ww*p.z; a3 += ww*p.w;
            }
        }
    }
    a0  += __shfl_xor_sync(FULL, a0, 16);
    a1v += __shfl_xor_sync(FULL, a1v, 16);
    a2v += __shfl_xor_sync(FULL, a2v, 16);
    a3  += __shfl_xor_sync(FULL, a3, 16);
#pragma unroll
    for (int o = 16; o; o >>= 1) den += __shfl_xor_sync(FULL, den, o);
    if (lane < 16) {
        float inv = 1.f / den;
        *(float4*)&out[(size_t)n*F2 + fl] =
            make_float4(a0*inv, a1v*inv, a2v*inv, a3*inv);
    }
}

// ---------------- launch -------------------------------------------------------
extern "C" void kernel_launch(void* const* d_in, const int* in_sizes, int n_in,
                              void* d_out, int out_size) {
    const float* x     = (const float*)d_in[0];
    const int*   edges = (const int*)d_in[1];
    const float* W1    = (const float*)d_in[2];
    const float* a1    = (const float*)d_in[3];
    const float* W2    = (const float*)d_in[4];
    const float* a2    = (const float*)d_in[5];
    float* out = (float*)d_out;

    static cudaStream_t s2 = nullptr;
    static cudaEvent_t evFork = nullptr, evCSR = nullptr;
    if (s2 == nullptr) {
        cudaStreamCreateWithFlags(&s2, cudaStreamNonBlocking);
        cudaEventCreateWithFlags(&evFork, cudaEventDisableTiming);
        cudaEventCreateWithFlags(&evCSR, cudaEventDisableTiming);
    }

    void* cnt_ptr = nullptr;
    cudaGetSymbolAddress(&cnt_ptr, g_cnt);

    // fork: CSR build on s2, concurrent with split+gemm1 on main stream
    cudaEventRecord(evFork, 0);
    cudaStreamWaitEvent(s2, evFork, 0);

    cudaMemsetAsync(cnt_ptr, 0, N_NODES*sizeof(int), s2);
    prep_edges<<<(NE + 255)/256, 256, 0, s2>>>(edges);
    scan_kernel<<<1, 1024, 0, s2>>>();
    fill_csr<<<(NE + 255)/256, 256, 0, s2>>>();
    cudaEventRecord(evCSR, s2);

    prep_splits<<<(NXP + 255)/256, 256>>>(W1, x);
    gemm1_kernel<<<dim3(H1, (N_NODES + 127)/128), 256>>>(a1);

    // join: gather1 needs CSR + gemm1
    cudaStreamWaitEvent(0, evCSR, 0);
    gather1<<<(N_NODES*H1*32 + 255)/256, 256>>>();

    // layer 2
    gemm2_kernel<<<dim3(1, (N_NODES + 63)/64, SPLITK), 256>>>(W2);
    alpha2_combine<<<(N_NODES*32 + 255)/256, 256>>>(a2);
    gather2<<<(N_NODES*32 + 255)/256, 256>>>(out);
}

// round 13
// speedup vs baseline: 1.2147x; 1.0303x over previous
#include <cuda_runtime.h>
#include <cuda_fp16.h>
#include <cstdint>

#define N_NODES 10000
#define DIN 128
#define H1 8
#define F1 64
#define C1 512            // H1*F1
#define E0 80000
#define NE (2*E0 + N_NODES)   // 170000
#define F2 64
#define NEG_SLOPE 0.2f
#define FULL 0xffffffffu
#define NXP (N_NODES*(DIN/2))    // 640000
#define SPLITK 8

// ---------------- scratch (static device globals; no allocation) -------------
static __device__ int      g_src[NE];
static __device__ int      g_dst[NE];
static __device__ int      g_cnt[N_NODES];
static __device__ int      g_cursor[N_NODES];
static __device__ int      g_rowptr[N_NODES + 1];
static __device__ int      g_nbr[NE];              // CSR by dst: src indices
static __device__ uint32_t g_XH[NXP];              // x fp16-split hi, [n][kpair]
static __device__ uint32_t g_XL[NXP];              // x fp16-split lo
static __device__ uint32_t g_B1H[(DIN/2)*C1];      // W1 fp16 (single plane), kpair-major
static __device__ __half2  g_P1h[N_NODES*(C1/2)];  // proj1 as fp16 pairs (gather feed)
static __device__ float    g_as1[N_NODES*H1];
static __device__ float    g_an1[N_NODES*H1];
static __device__ float    g_hbuf[N_NODES*C1];     // layer-1 output (post ELU), fp32
static __device__ float    g_p2part[SPLITK*N_NODES*F2]; // split-K partials for gemm2
static __device__ float    g_proj2[N_NODES*F2];
static __device__ float    g_as2[N_NODES];
static __device__ float    g_an2[N_NODES];

// fp16 split: v = hi + lo, hi/lo fp16; lo captures next ~11 mantissa bits
__device__ __forceinline__ void split_pack_f16(float v0, float v1,
                                               uint32_t& hi, uint32_t& lo) {
    __half2 h2 = __floats2half2_rn(v0, v1);
    float r0 = v0 - __half2float(__low2half(h2));
    float r1 = v1 - __half2float(__high2half(h2));
    __half2 l2 = __floats2half2_rn(r0, r1);
    hi = *(const uint32_t*)&h2;
    lo = *(const uint32_t*)&l2;
}

// ---------------- prep A: edge decode + degree count (stream 2) --------------
__global__ void prep_edges(const int* __restrict__ e32) {
    int i = blockIdx.x * blockDim.x + threadIdx.x;
    if (i >= NE) return;
    bool is64 = (e32[1] == 0) && (e32[3] == 0) && (e32[5] == 0) && (e32[7] == 0);
    int s, d;
    if (i < NE - N_NODES) {
        int j  = (i < E0) ? i : (i - E0);
        int si = (i < E0) ? j : (E0 + j);
        int di = (i < E0) ? (E0 + j) : j;
        s = is64 ? e32[2*si] : e32[si];
        d = is64 ? e32[2*di] : e32[di];
    } else {
        s = i - (NE - N_NODES); d = s;
    }
    s = min(max(s, 0), N_NODES - 1);
    d = min(max(d, 0), N_NODES - 1);
    g_src[i] = s; g_dst[i] = d;
    atomicAdd(&g_cnt[d], 1);
}

// ---------------- prep B: x fp16-split + W1 fp16 (main stream) ---------------
__global__ void prep_splits(const float* __restrict__ W1,
                            const float* __restrict__ x) {
    int i = blockIdx.x * blockDim.x + threadIdx.x;
    if (i < NXP) {
        float2 v = *(const float2*)&x[2*i];
        split_pack_f16(v.x, v.y, g_XH[i], g_XL[i]);
    }
    if (i < (DIN/2)*C1) {
        int kp = i / C1, c = i % C1;
        int h = c >> 6, f = c & 63;
        float v0 = W1[(h*DIN + 2*kp)*F1 + f];
        float v1 = W1[(h*DIN + 2*kp + 1)*F1 + f];
        __half2 h2 = __floats2half2_rn(v0, v1);
        g_B1H[i] = *(const uint32_t*)&h2;
    }
}

// ---------------- exclusive scan of in-degrees (single block) ----------------
__global__ void scan_kernel() {
    __shared__ int ssum[1024];
    const int t = threadIdx.x;
    const int per = (N_NODES + 1023) / 1024;   // 10
    int base = t * per;
    int loc[16];
    int s = 0;
#pragma unroll
    for (int i = 0; i < per; i++) {
        int idx = base + i;
        int v = (idx < N_NODES) ? g_cnt[idx] : 0;
        loc[i] = v; s += v;
    }
    ssum[t] = s;
    __syncthreads();
    for (int off = 1; off < 1024; off <<= 1) {
        int v = (t >= off) ? ssum[t - off] : 0;
        __syncthreads();
        ssum[t] += v;
        __syncthreads();
    }
    int run = (t > 0) ? ssum[t - 1] : 0;
#pragma unroll
    for (int i = 0; i < per; i++) {
        int idx = base + i;
        if (idx < N_NODES) { g_rowptr[idx] = run; g_cursor[idx] = run; run += loc[i]; }
    }
    if (t == 1023) g_rowptr[N_NODES] = NE;
}

__global__ void fill_csr() {
    int e = blockIdx.x * blockDim.x + threadIdx.x;
    if (e >= NE) return;
    int d = g_dst[e];
    int slot = atomicAdd(&g_cursor[d], 1);   // cursor pre-seeded with rowptr
    g_nbr[slot] = g_src[e];
}

// ---------------- fp16 tensor-core MMA (m16n8k16) -----------------------------
#define MMA_F16(D, A0, A1, A2, A3, B0, B1) \
    asm("mma.sync.aligned.m16n8k16.row.col.f32.f16.f16.f32 " \
        "{%0,%1,%2,%3}, {%4,%5,%6,%7}, {%8,%9}, {%0,%1,%2,%3};" \
        : "+f"(D[0]), "+f"(D[1]), "+f"(D[2]), "+f"(D[3]) \
        : "r"(A0), "r"(A1), "r"(A2), "r"(A3), "r"(B0), "r"(B1))

// ---------------- GEMM1: 128x64 tile, fp16-x2 split, fused alpha1 ------------
__global__ __launch_bounds__(256) void gemm1_kernel(const float* __restrict__ a1) {
    __shared__ uint32_t AsH[128][12], AsL[128][12];
    __shared__ uint32_t BsH[64][12];
    __shared__ float sAs[64], sAn[64];
    __shared__ float salS[128][2], salN[128][2];

    const int tid = threadIdx.x;
    const int lane = tid & 31, wid = tid >> 5;
    const int wm = wid >> 1, wn = wid & 1;
    const int g = lane >> 2, tig = lane & 3;
    const int row0 = blockIdx.y * 128;
    const int h = blockIdx.x;
    const int col0 = h * 64;
    const int M = N_NODES;

    if (tid < 64) {
        sAs[tid] = __ldg(&a1[h*2*F1 + tid]);
        sAn[tid] = __ldg(&a1[h*2*F1 + F1 + tid]);
    }

    float acc[2][4][4];
#pragma unroll
    for (int mi = 0; mi < 2; mi++)
#pragma unroll
        for (int ni = 0; ni < 4; ni++)
#pragma unroll
            for (int q = 0; q < 4; q++) acc[mi][ni][q] = 0.f;

    for (int k0 = 0; k0 < DIN; k0 += 16) {
        const int kpb = k0 >> 1;
#pragma unroll
        for (int t = 0; t < 4; t++) {
            int idx = tid + t*256;
            int r = idx >> 3, kk = idx & 7;
            int grow = row0 + r;
            if (grow < M) {
                size_t gi = (size_t)grow*(DIN/2) + kpb + kk;
                AsH[r][kk] = g_XH[gi];
                AsL[r][kk] = g_XL[gi];
            } else {
                AsH[r][kk] = 0u; AsL[r][kk] = 0u;
            }
        }
#pragma unroll
        for (int t = 0; t < 2; t++) {
            int idx = tid + t*256;
            int kk = idx >> 6, c = idx & 63;
            BsH[c][kk] = g_B1H[(size_t)(kpb + kk)*C1 + col0 + c];
        }
        __syncthreads();

        uint32_t bh[4][2];
#pragma unroll
        for (int ni = 0; ni < 4; ni++) {
            int c = wn*32 + ni*8 + g;
            bh[ni][0] = BsH[c][tig];     bh[ni][1] = BsH[c][tig + 4];
        }
#pragma unroll
        for (int mi = 0; mi < 2; mi++) {
            int r = wm*32 + mi*16 + g;
            uint32_t ah0 = AsH[r][tig],     ah1 = AsH[r + 8][tig];
            uint32_t ah2 = AsH[r][tig + 4], ah3 = AsH[r + 8][tig + 4];
            uint32_t al0 = AsL[r][tig],     al1 = AsL[r + 8][tig];
            uint32_t al2 = AsL[r][tig + 4], al3 = AsL[r + 8][tig + 4];
#pragma unroll
            for (int ni = 0; ni < 4; ni++) {
                MMA_F16(acc[mi][ni], ah0, ah1, ah2, ah3, bh[ni][0], bh[ni][1]);
                MMA_F16(acc[mi][ni], al0, al1, al2, al3, bh[ni][0], bh[ni][1]);
            }
        }
        __syncthreads();
    }

    // epilogue: fp16 proj1 store + fused alpha1 (fp32)
#pragma unroll
    for (int mi = 0; mi < 2; mi++) {
        float s0 = 0.f, s8 = 0.f, n0 = 0.f, n8 = 0.f;
        int growA = row0 + wm*32 + mi*16 + g;
        int growB = growA + 8;
#pragma unroll
        for (int ni = 0; ni < 4; ni++) {
            float c0 = acc[mi][ni][0], c1 = acc[mi][ni][1];
            float c2 = acc[mi][ni][2], c3 = acc[mi][ni][3];
            int cl = wn*32 + ni*8 + 2*tig;
            size_t cp = (size_t)(col0 + cl) >> 1;
            if (growA < M)
                g_P1h[(size_t)growA*(C1/2) + cp] = __floats2half2_rn(c0, c1);
            if (growB < M)
                g_P1h[(size_t)growB*(C1/2) + cp] = __floats2half2_rn(c2, c3);
            float as0 = sAs[cl], as1 = sAs[cl + 1];
            float an0 = sAn[cl], an1 = sAn[cl + 1];
            s0 += c0*as0 + c1*as1;  n0 += c0*an0 + c1*an1;
            s8 += c2*as0 + c3*as1;  n8 += c2*an0 + c3*an1;
        }
#pragma unroll
        for (int o = 1; o <= 2; o <<= 1) {
            s0 += __shfl_xor_sync(FULL, s0, o);
            s8 += __shfl_xor_sync(FULL, s8, o);
            n0 += __shfl_xor_sync(FULL, n0, o);
            n8 += __shfl_xor_sync(FULL, n8, o);
        }
        if (tig == 0) {
            int rl = wm*32 + mi*16 + g;
            salS[rl][wn] = s0;  salN[rl][wn] = n0;
            salS[rl + 8][wn] = s8;  salN[rl + 8][wn] = n8;
        }
    }
    __syncthreads();
    if (tid < 128) {
        int grow = row0 + tid;
        if (grow < M) {
            g_as1[grow*H1 + h] = salS[tid][0] + salS[tid][1];
            g_an1[grow*H1 + h] = salN[tid][0] + salN[tid][1];
        }
    }
}

// ---------------- GEMM2 split-K SIMT: 64x64 tile, K-chunk 64 per z -----------
__global__ void gemm2_kernel(const float* __restrict__ B) {
    __shared__ __align__(16) float As[16][68];
    __shared__ __align__(16) float Bs[16][64];
    const float* A = g_hbuf;
    const int M = N_NODES, N = F2, K = C1;
    const int tid = threadIdx.x;
    const int tx = tid & 15, ty = tid >> 4;
    const int row0 = blockIdx.y * 64;
    const int kz0 = blockIdx.z * (K/SPLITK);
    float* C = g_p2part + (size_t)blockIdx.z * N_NODES * F2;
    float acc[4][4];
#pragma unroll
    for (int i = 0; i < 4; i++)
#pragma unroll
        for (int j = 0; j < 4; j++) acc[i][j] = 0.f;

    for (int k0 = kz0; k0 < kz0 + K/SPLITK; k0 += 16) {
#pragma unroll
        for (int l = 0; l < 4; l++) {
            int i = tid + l*256;
            int r = i >> 4, kk = i & 15;
            int gr = row0 + r;
            As[kk][r] = (gr < M) ? A[(size_t)gr*K + k0 + kk] : 0.f;
        }
        {
            int kk = tid >> 6, c = tid & 63;
            Bs[kk][c]      = B[(size_t)(k0 + kk)*N + c];
            Bs[kk + 4][c]  = B[(size_t)(k0 + kk + 4)*N + c];
            Bs[kk + 8][c]  = B[(size_t)(k0 + kk + 8)*N + c];
            Bs[kk + 12][c] = B[(size_t)(k0 + kk + 12)*N + c];
        }
        __syncthreads();
#pragma unroll
        for (int kk = 0; kk < 16; kk++) {
            float4 av = *(const float4*)&As[kk][ty*4];
            float4 bv = *(const float4*)&Bs[kk][tx*4];
            float a[4] = {av.x, av.y, av.z, av.w};
            float b[4] = {bv.x, bv.y, bv.z, bv.w};
#pragma unroll
            for (int i = 0; i < 4; i++)
#pragma unroll
                for (int j = 0; j < 4; j++) acc[i][j] += a[i]*b[j];
        }
        __syncthreads();
    }
#pragma unroll
    for (int i = 0; i < 4; i++) {
        int gr = row0 + ty*4 + i;
        if (gr < M) {
            *(float4*)&C[(size_t)gr*N + tx*4] =
                make_float4(acc[i][0], acc[i][1], acc[i][2], acc[i][3]);
        }
    }
}

// ---------------- combine split-K partials + attention (layer 2) -------------
__global__ void alpha2_combine(const float* __restrict__ a2) {
    int t = blockIdx.x * blockDim.x + threadIdx.x;
    int w = t >> 5, lane = t & 31;
    if (w >= N_NODES) return;
    const size_t NF = (size_t)N_NODES * F2;
    size_t base = (size_t)w*F2;
    float v0 = 0.f, v1 = 0.f;
#pragma unroll
    for (int z = 0; z < SPLITK; z++) {
        v0 += g_p2part[z*NF + base + lane];
        v1 += g_p2part[z*NF + base + lane + 32];
    }
    g_proj2[base + lane] = v0;
    g_proj2[base + lane + 32] = v1;
    float s  = v0*a2[lane]      + v1*a2[lane + 32];
    float tn = v0*a2[F2 + lane] + v1*a2[F2 + lane + 32];
#pragma unroll
    for (int o = 16; o; o >>= 1) {
        s  += __shfl_xor_sync(FULL, s, o);
        tn += __shfl_xor_sync(FULL, tn, o);
    }
    if (!lane) { g_as2[w] = s; g_an2[w] = tn; }
}

// ---------------- fused gather1: single-pass softmax (no max shift) ----------
__global__ void gather1() {
    int t = blockIdx.x * blockDim.x + threadIdx.x;
    int w = t >> 5, lane = t & 31;
    if (w >= N_NODES*H1) return;
    int n = w >> 3, h = w & 7;
    int beg = g_rowptr[n], end = g_rowptr[n + 1];
    float as = g_as1[n*H1 + h];

    const int half = lane >> 4;
    const int fl2 = (lane & 15) * 2;
    const __half2* projh = g_P1h + h*(F1/2) + fl2;
    float a0 = 0.f, a1v = 0.f, a2v = 0.f, a3 = 0.f, den = 0.f;
    for (int base = beg; base < end; base += 32) {
        int i = base + lane;
        int s = 0; float wgt = 0.f;
        if (i < end) {
            s = g_nbr[i];
            float v = as + g_an1[s*H1 + h];
            v = (v >= 0.f) ? v : NEG_SLOPE*v;
            wgt = __expf(v);
            den += wgt;
        }
        int cnt = min(32, end - base);
        if (cnt == 32) {
#pragma unroll
            for (int j = 0; j < 16; j++) {
                int sl = 2*j + half;
                float ww = __shfl_sync(FULL, wgt, sl);
                int ss = __shfl_sync(FULL, s, sl);
                uint2 u = *(const uint2*)&projh[(size_t)ss*(C1/2)];
                float2 f0 = __half22float2(*reinterpret_cast<__half2*>(&u.x));
                float2 f1 = __half22float2(*reinterpret_cast<__half2*>(&u.y));
                a0 += ww*f0.x; a1v += ww*f0.y; a2v += ww*f1.x; a3 += ww*f1.y;
            }
        } else {
            int jmax = (cnt + 1) >> 1;
            for (int j = 0; j < jmax; j++) {
                int sl = 2*j + half;
                float ww = __shfl_sync(FULL, wgt, sl);
                int ss = __shfl_sync(FULL, s, sl);
                uint2 u = *(const uint2*)&projh[(size_t)ss*(C1/2)];
                float2 f0 = __half22float2(*reinterpret_cast<__half2*>(&u.x));
                float2 f1 = __half22float2(*reinterpret_cast<__half2*>(&u.y));
                a0 += ww*f0.x; a1v += ww*f0.y; a2v += ww*f1.x; a3 += ww*f1.y;
            }
        }
    }
    a0  += __shfl_xor_sync(FULL, a0, 16);
    a1v += __shfl_xor_sync(FULL, a1v, 16);
    a2v += __shfl_xor_sync(FULL, a2v, 16);
    a3  += __shfl_xor_sync(FULL, a3, 16);
#pragma unroll
    for (int o = 16; o; o >>= 1) den += __shfl_xor_sync(FULL, den, o);
    if (lane < 16) {
        float inv = 1.f / den;
        a0 *= inv; a1v *= inv; a2v *= inv; a3 *= inv;
        a0  = (a0  > 0.f) ? a0  : expm1f(a0);
        a1v = (a1v > 0.f) ? a1v : expm1f(a1v);
        a2v = (a2v > 0.f) ? a2v : expm1f(a2v);
        a3  = (a3  > 0.f) ? a3  : expm1f(a3);
        *(float4*)&g_hbuf[(size_t)n*C1 + h*F1 + fl2*2] = make_float4(a0, a1v, a2v, a3);
    }
}

// ---------------- fused gather layer 2 (single-pass, fp32 features) ----------
__global__ void gather2(float* __restrict__ out) {
    int t = blockIdx.x * blockDim.x + threadIdx.x;
    int w = t >> 5, lane = t & 31;
    if (w >= N_NODES) return;
    int n = w;
    int beg = g_rowptr[n], end = g_rowptr[n + 1];
    float as = g_as2[n];

    const int half = lane >> 4;
    const int fl = (lane & 15) * 4;
    const float* projl = g_proj2 + fl;
    float a0 = 0.f, a1v = 0.f, a2v = 0.f, a3 = 0.f, den = 0.f;
    for (int base = beg; base < end; base += 32) {
        int i = base + lane;
        int s = 0; float wgt = 0.f;
        if (i < end) {
            s = g_nbr[i];
            float v = as + g_an2[s];
            v = (v >= 0.f) ? v : NEG_SLOPE*v;
            wgt = __expf(v);
            den += wgt;
        }
        int cnt = min(32, end - base);
        if (cnt == 32) {
#pragma unroll
            for (int j = 0; j < 16; j++) {
                int sl = 2*j + half;
                float ww = __shfl_sync(FULL, wgt, sl);
                int ss = __shfl_sync(FULL, s, sl);
                float4 p = *(const float4*)&projl[(size_t)ss*F2];
                a0 += ww*p.x; a1v += ww*p.y; a2v += ww*p.z; a3 += ww*p.w;
            }
        } else {
            int jmax = (cnt + 1) >> 1;
            for (int j = 0; j < jmax; j++) {
                int sl = 2*j + half;
                float ww = __shfl_sync(FULL, wgt, sl);
                int ss = __shfl_sync(FULL, s, sl);
                float4 p = *(const float4*)&projl[(size_t)ss*F2];
                a0 += ww*p.x; a1v += ww*p.y; a2v += ww*p.z; a3 += ww*p.w;
            }
        }
    }
    a0  += __shfl_xor_sync(FULL, a0, 16);
    a1v += __shfl_xor_sync(FULL, a1v, 16);
    a2v += __shfl_xor_sync(FULL, a2v, 16);
    a3  += __shfl_xor_sync(FULL, a3, 16);
#pragma unroll
    for (int o = 16; o; o >>= 1) den += __shfl_xor_sync(FULL, den, o);
    if (lane < 16) {
        float inv = 1.f / den;
        *(float4*)&out[(size_t)n*F2 + fl] =
            make_float4(a0*inv, a1v*inv, a2v*inv, a3*inv);
    }
}

// ---------------- launch -------------------------------------------------------
extern "C" void kernel_launch(void* const* d_in, const int* in_sizes, int n_in,
                              void* d_out, int out_size) {
    const float* x     = (const float*)d_in[0];
    const int*   edges = (const int*)d_in[1];
    const float* W1    = (const float*)d_in[2];
    const float* a1    = (const float*)d_in[3];
    const float* W2    = (const float*)d_in[4];
    const float* a2    = (const float*)d_in[5];
    float* out = (float*)d_out;

    static cudaStream_t s2 = nullptr;
    static cudaEvent_t evFork = nullptr, evCSR = nullptr;
    if (s2 == nullptr) {
        cudaStreamCreateWithFlags(&s2, cudaStreamNonBlocking);
        cudaEventCreateWithFlags(&evFork, cudaEventDisableTiming);
        cudaEventCreateWithFlags(&evCSR, cudaEventDisableTiming);
    }

    void* cnt_ptr = nullptr;
    cudaGetSymbolAddress(&cnt_ptr, g_cnt);

    // fork: CSR build on s2, concurrent with split+gemm1 on main stream
    cudaEventRecord(evFork, 0);
    cudaStreamWaitEvent(s2, evFork, 0);

    cudaMemsetAsync(cnt_ptr, 0, N_NODES*sizeof(int), s2);
    prep_edges<<<(NE + 255)/256, 256, 0, s2>>>(edges);
    scan_kernel<<<1, 1024, 0, s2>>>();
    fill_csr<<<(NE + 255)/256, 256, 0, s2>>>();
    cudaEventRecord(evCSR, s2);

    prep_splits<<<(NXP + 255)/256, 256>>>(W1, x);
    gemm1_kernel<<<dim3(H1, (N_NODES + 127)/128), 256>>>(a1);

    // join: gather1 needs CSR + gemm1
    cudaStreamWaitEvent(0, evCSR, 0);
    gather1<<<(N_NODES*H1*32 + 255)/256, 256>>>();

    // layer 2
    gemm2_kernel<<<dim3(1, (N_NODES + 63)/64, SPLITK), 256>>>(W2);
    alpha2_combine<<<(N_NODES*32 + 255)/256, 256>>>(a2);
    gather2<<<(N_NODES*32 + 255)/256, 256>>>(out);
}

// round 14
// speedup vs baseline: 1.3070x; 1.0760x over previous
#include <cuda_runtime.h>
#include <cuda_fp16.h>
#include <cstdint>

#define N_NODES 10000
#define DIN 128
#define H1 8
#define F1 64
#define C1 512            // H1*F1
#define E0 80000
#define NE (2*E0 + N_NODES)   // 170000
#define F2 64
#define NEG_SLOPE 0.2f
#define FULL 0xffffffffu
#define NXP (N_NODES*(DIN/2))    // 640000
#define ZK2 4                    // gemm2 split-K planes

// ---------------- scratch (static device globals; no allocation) -------------
static __device__ int      g_src[NE];
static __device__ int      g_dst[NE];
static __device__ int      g_cnt[N_NODES];
static __device__ int      g_cursor[N_NODES];
static __device__ int      g_rowptr[N_NODES + 1];
static __device__ int      g_nbr[NE];              // CSR by dst: src indices
static __device__ uint32_t g_XH[NXP];              // x fp16-split hi, [n][kpair]
static __device__ uint32_t g_XL[NXP];              // x fp16-split lo
static __device__ uint32_t g_B1H[(DIN/2)*C1];      // W1 fp16 plane, kpair-major
static __device__ uint32_t g_B2H[(C1/2)*F2];       // W2 fp16 plane, kpair-major
static __device__ __half2  g_P1h[N_NODES*(C1/2)];  // proj1 as fp16 pairs (gather feed)
static __device__ float    g_as1[N_NODES*H1];
static __device__ float    g_an1[N_NODES*H1];
static __device__ uint32_t g_HH[N_NODES*(C1/2)];   // hbuf fp16-split hi (from gather1)
static __device__ uint32_t g_HL[N_NODES*(C1/2)];   // hbuf fp16-split lo
static __device__ float    g_p2part[ZK2*N_NODES*F2]; // gemm2 split-K partials
static __device__ float    g_proj2[N_NODES*F2];
static __device__ float    g_as2[N_NODES];
static __device__ float    g_an2[N_NODES];

// fp16 split: v = hi + lo
__device__ __forceinline__ void split_pack_f16(float v0, float v1,
                                               uint32_t& hi, uint32_t& lo) {
    __half2 h2 = __floats2half2_rn(v0, v1);
    float r0 = v0 - __half2float(__low2half(h2));
    float r1 = v1 - __half2float(__high2half(h2));
    __half2 l2 = __floats2half2_rn(r0, r1);
    hi = *(const uint32_t*)&h2;
    lo = *(const uint32_t*)&l2;
}

// ---------------- prep A: edge decode + degree count (stream 2) --------------
__global__ void prep_edges(const int* __restrict__ e32) {
    int i = blockIdx.x * blockDim.x + threadIdx.x;
    if (i >= NE) return;
    bool is64 = (e32[1] == 0) && (e32[3] == 0) && (e32[5] == 0) && (e32[7] == 0);
    int s, d;
    if (i < NE - N_NODES) {
        int j  = (i < E0) ? i : (i - E0);
        int si = (i < E0) ? j : (E0 + j);
        int di = (i < E0) ? (E0 + j) : j;
        s = is64 ? e32[2*si] : e32[si];
        d = is64 ? e32[2*di] : e32[di];
    } else {
        s = i - (NE - N_NODES); d = s;
    }
    s = min(max(s, 0), N_NODES - 1);
    d = min(max(d, 0), N_NODES - 1);
    g_src[i] = s; g_dst[i] = d;
    atomicAdd(&g_cnt[d], 1);
}

// ---------------- prep B: x fp16-split (vectorized) + W1/W2 fp16 -------------
__global__ void prep_splits(const float* __restrict__ W1,
                            const float* __restrict__ W2,
                            const float* __restrict__ x) {
    int i = blockIdx.x * blockDim.x + threadIdx.x;
    if (i < NXP/2) {                     // 2 kpairs per thread via float4
        float4 v = *(const float4*)&x[4*i];
        uint32_t h0, l0, h1, l1;
        split_pack_f16(v.x, v.y, h0, l0);
        split_pack_f16(v.z, v.w, h1, l1);
        *(uint2*)&g_XH[2*i] = make_uint2(h0, h1);
        *(uint2*)&g_XL[2*i] = make_uint2(l0, l1);
    }
    if (i < (DIN/2)*C1) {
        int kp = i / C1, c = i % C1;
        int h = c >> 6, f = c & 63;
        __half2 h2 = __floats2half2_rn(W1[(h*DIN + 2*kp)*F1 + f],
                                       W1[(h*DIN + 2*kp + 1)*F1 + f]);
        g_B1H[i] = *(const uint32_t*)&h2;
    }
    if (i < (C1/2)*F2) {
        int kp = i / F2, c = i % F2;
        __half2 h2 = __floats2half2_rn(W2[(2*kp)*F2 + c],
                                       W2[(2*kp + 1)*F2 + c]);
        g_B2H[i] = *(const uint32_t*)&h2;
    }
}

// ---------------- exclusive scan of in-degrees (single block) ----------------
__global__ void scan_kernel() {
    __shared__ int ssum[1024];
    const int t = threadIdx.x;
    const int per = (N_NODES + 1023) / 1024;   // 10
    int base = t * per;
    int loc[16];
    int s = 0;
#pragma unroll
    for (int i = 0; i < per; i++) {
        int idx = base + i;
        int v = (idx < N_NODES) ? g_cnt[idx] : 0;
        loc[i] = v; s += v;
    }
    ssum[t] = s;
    __syncthreads();
    for (int off = 1; off < 1024; off <<= 1) {
        int v = (t >= off) ? ssum[t - off] : 0;
        __syncthreads();
        ssum[t] += v;
        __syncthreads();
    }
    int run = (t > 0) ? ssum[t - 1] : 0;
#pragma unroll
    for (int i = 0; i < per; i++) {
        int idx = base + i;
        if (idx < N_NODES) { g_rowptr[idx] = run; g_cursor[idx] = run; run += loc[i]; }
    }
    if (t == 1023) g_rowptr[N_NODES] = NE;
}

__global__ void fill_csr() {
    int e = blockIdx.x * blockDim.x + threadIdx.x;
    if (e >= NE) return;
    int d = g_dst[e];
    int slot = atomicAdd(&g_cursor[d], 1);
    g_nbr[slot] = g_src[e];
}

// ---------------- fp16 tensor-core MMA (m16n8k16) -----------------------------
#define MMA_F16(D, A0, A1, A2, A3, B0, B1) \
    asm("mma.sync.aligned.m16n8k16.row.col.f32.f16.f16.f32 " \
        "{%0,%1,%2,%3}, {%4,%5,%6,%7}, {%8,%9}, {%0,%1,%2,%3};" \
        : "+f"(D[0]), "+f"(D[1]), "+f"(D[2]), "+f"(D[3]) \
        : "r"(A0), "r"(A1), "r"(A2), "r"(A3), "r"(B0), "r"(B1))

// ---------------- GEMM1: 128x64 tile, fp16-x2 split, fused alpha1 ------------
__global__ __launch_bounds__(256) void gemm1_kernel(const float* __restrict__ a1) {
    __shared__ uint32_t AsH[128][12], AsL[128][12];
    __shared__ uint32_t BsH[64][12];
    __shared__ float sAs[64], sAn[64];
    __shared__ float salS[128][2], salN[128][2];

    const int tid = threadIdx.x;
    const int lane = tid & 31, wid = tid >> 5;
    const int wm = wid >> 1, wn = wid & 1;
    const int g = lane >> 2, tig = lane & 3;
    const int row0 = blockIdx.y * 128;
    const int h = blockIdx.x;
    const int col0 = h * 64;
    const int M = N_NODES;

    if (tid < 64) {
        sAs[tid] = __ldg(&a1[h*2*F1 + tid]);
        sAn[tid] = __ldg(&a1[h*2*F1 + F1 + tid]);
    }

    float acc[2][4][4];
#pragma unroll
    for (int mi = 0; mi < 2; mi++)
#pragma unroll
        for (int ni = 0; ni < 4; ni++)
#pragma unroll
            for (int q = 0; q < 4; q++) acc[mi][ni][q] = 0.f;

    for (int k0 = 0; k0 < DIN; k0 += 16) {
        const int kpb = k0 >> 1;
#pragma unroll
        for (int t = 0; t < 4; t++) {
            int idx = tid + t*256;
            int r = idx >> 3, kk = idx & 7;
            int grow = row0 + r;
            if (grow < M) {
                size_t gi = (size_t)grow*(DIN/2) + kpb + kk;
                AsH[r][kk] = g_XH[gi];
                AsL[r][kk] = g_XL[gi];
            } else {
                AsH[r][kk] = 0u; AsL[r][kk] = 0u;
            }
        }
#pragma unroll
        for (int t = 0; t < 2; t++) {
            int idx = tid + t*256;
            int kk = idx >> 6, c = idx & 63;
            BsH[c][kk] = g_B1H[(size_t)(kpb + kk)*C1 + col0 + c];
        }
        __syncthreads();

        uint32_t bh[4][2];
#pragma unroll
        for (int ni = 0; ni < 4; ni++) {
            int c = wn*32 + ni*8 + g;
            bh[ni][0] = BsH[c][tig];     bh[ni][1] = BsH[c][tig + 4];
        }
#pragma unroll
        for (int mi = 0; mi < 2; mi++) {
            int r = wm*32 + mi*16 + g;
            uint32_t ah0 = AsH[r][tig],     ah1 = AsH[r + 8][tig];
            uint32_t ah2 = AsH[r][tig + 4], ah3 = AsH[r + 8][tig + 4];
            uint32_t al0 = AsL[r][tig],     al1 = AsL[r + 8][tig];
            uint32_t al2 = AsL[r][tig + 4], al3 = AsL[r + 8][tig + 4];
#pragma unroll
            for (int ni = 0; ni < 4; ni++) {
                MMA_F16(acc[mi][ni], ah0, ah1, ah2, ah3, bh[ni][0], bh[ni][1]);
                MMA_F16(acc[mi][ni], al0, al1, al2, al3, bh[ni][0], bh[ni][1]);
            }
        }
        __syncthreads();
    }

    // epilogue: fp16 proj1 store + fused alpha1 (fp32)
#pragma unroll
    for (int mi = 0; mi < 2; mi++) {
        float s0 = 0.f, s8 = 0.f, n0 = 0.f, n8 = 0.f;
        int growA = row0 + wm*32 + mi*16 + g;
        int growB = growA + 8;
#pragma unroll
        for (int ni = 0; ni < 4; ni++) {
            float c0 = acc[mi][ni][0], c1 = acc[mi][ni][1];
            float c2 = acc[mi][ni][2], c3 = acc[mi][ni][3];
            int cl = wn*32 + ni*8 + 2*tig;
            size_t cp = (size_t)(col0 + cl) >> 1;
            if (growA < M)
                g_P1h[(size_t)growA*(C1/2) + cp] = __floats2half2_rn(c0, c1);
            if (growB < M)
                g_P1h[(size_t)growB*(C1/2) + cp] = __floats2half2_rn(c2, c3);
            float as0 = sAs[cl], as1 = sAs[cl + 1];
            float an0 = sAn[cl], an1 = sAn[cl + 1];
            s0 += c0*as0 + c1*as1;  n0 += c0*an0 + c1*an1;
            s8 += c2*as0 + c3*as1;  n8 += c2*an0 + c3*an1;
        }
#pragma unroll
        for (int o = 1; o <= 2; o <<= 1) {
            s0 += __shfl_xor_sync(FULL, s0, o);
            s8 += __shfl_xor_sync(FULL, s8, o);
            n0 += __shfl_xor_sync(FULL, n0, o);
            n8 += __shfl_xor_sync(FULL, n8, o);
        }
        if (tig == 0) {
            int rl = wm*32 + mi*16 + g;
            salS[rl][wn] = s0;  salN[rl][wn] = n0;
            salS[rl + 8][wn] = s8;  salN[rl + 8][wn] = n8;
        }
    }
    __syncthreads();
    if (tid < 128) {
        int grow = row0 + tid;
        if (grow < M) {
            g_as1[grow*H1 + h] = salS[tid][0] + salS[tid][1];
            g_an1[grow*H1 + h] = salN[tid][0] + salN[tid][1];
        }
    }
}

// ---------------- GEMM2: fp16-x2 MMA, split-K z=4, pre-split A ---------------
__global__ __launch_bounds__(256) void gemm2_kernel() {
    __shared__ uint32_t AsH[128][12], AsL[128][12];
    __shared__ uint32_t BsH[64][12];

    const int tid = threadIdx.x;
    const int lane = tid & 31, wid = tid >> 5;
    const int wm = wid >> 1, wn = wid & 1;
    const int g = lane >> 2, tig = lane & 3;
    const int row0 = blockIdx.y * 128;
    const int z = blockIdx.x;
    const int M = N_NODES;
    float* C = g_p2part + (size_t)z * N_NODES * F2;

    float acc[2][4][4];
#pragma unroll
    for (int mi = 0; mi < 2; mi++)
#pragma unroll
        for (int ni = 0; ni < 4; ni++)
#pragma unroll
            for (int q = 0; q < 4; q++) acc[mi][ni][q] = 0.f;

    const int kbeg = z * (C1/ZK2);           // 128 K per z
    for (int k0 = kbeg; k0 < kbeg + C1/ZK2; k0 += 16) {
        const int kpb = k0 >> 1;
#pragma unroll
        for (int t = 0; t < 4; t++) {
            int idx = tid + t*256;
            int r = idx >> 3, kk = idx & 7;
            int grow = row0 + r;
            if (grow < M) {
                size_t gi = (size_t)grow*(C1/2) + kpb + kk;
                AsH[r][kk] = g_HH[gi];
                AsL[r][kk] = g_HL[gi];
            } else {
                AsH[r][kk] = 0u; AsL[r][kk] = 0u;
            }
        }
#pragma unroll
        for (int t = 0; t < 2; t++) {
            int idx = tid + t*256;
            int kk = idx >> 6, c = idx & 63;
            BsH[c][kk] = g_B2H[(size_t)(kpb + kk)*F2 + c];
        }
        __syncthreads();

        uint32_t bh[4][2];
#pragma unroll
        for (int ni = 0; ni < 4; ni++) {
            int c = wn*32 + ni*8 + g;
            bh[ni][0] = BsH[c][tig];     bh[ni][1] = BsH[c][tig + 4];
        }
#pragma unroll
        for (int mi = 0; mi < 2; mi++) {
            int r = wm*32 + mi*16 + g;
            uint32_t ah0 = AsH[r][tig],     ah1 = AsH[r + 8][tig];
            uint32_t ah2 = AsH[r][tig + 4], ah3 = AsH[r + 8][tig + 4];
            uint32_t al0 = AsL[r][tig],     al1 = AsL[r + 8][tig];
            uint32_t al2 = AsL[r][tig + 4], al3 = AsL[r + 8][tig + 4];
#pragma unroll
            for (int ni = 0; ni < 4; ni++) {
                MMA_F16(acc[mi][ni], ah0, ah1, ah2, ah3, bh[ni][0], bh[ni][1]);
                MMA_F16(acc[mi][ni], al0, al1, al2, al3, bh[ni][0], bh[ni][1]);
            }
        }
        __syncthreads();
    }

    // store fp32 partials
#pragma unroll
    for (int mi = 0; mi < 2; mi++) {
        int growA = row0 + wm*32 + mi*16 + g;
        int growB = growA + 8;
#pragma unroll
        for (int ni = 0; ni < 4; ni++) {
            int cl = wn*32 + ni*8 + 2*tig;
            if (growA < M)
                *(float2*)&C[(size_t)growA*F2 + cl] =
                    make_float2(acc[mi][ni][0], acc[mi][ni][1]);
            if (growB < M)
                *(float2*)&C[(size_t)growB*F2 + cl] =
                    make_float2(acc[mi][ni][2], acc[mi][ni][3]);
        }
    }
}

// ---------------- combine split-K partials + attention (layer 2) -------------
__global__ void alpha2_combine(const float* __restrict__ a2) {
    int t = blockIdx.x * blockDim.x + threadIdx.x;
    int w = t >> 5, lane = t & 31;
    if (w >= N_NODES) return;
    const size_t NF = (size_t)N_NODES * F2;
    size_t base = (size_t)w*F2;
    float v0 = 0.f, v1 = 0.f;
#pragma unroll
    for (int z = 0; z < ZK2; z++) {
        v0 += g_p2part[z*NF + base + lane];
        v1 += g_p2part[z*NF + base + lane + 32];
    }
    g_proj2[base + lane] = v0;
    g_proj2[base + lane + 32] = v1;
    float s  = v0*a2[lane]      + v1*a2[lane + 32];
    float tn = v0*a2[F2 + lane] + v1*a2[F2 + lane + 32];
#pragma unroll
    for (int o = 16; o; o >>= 1) {
        s  += __shfl_xor_sync(FULL, s, o);
        tn += __shfl_xor_sync(FULL, tn, o);
    }
    if (!lane) { g_as2[w] = s; g_an2[w] = tn; }
}

// ---------------- fused gather1: single-pass softmax, fp16-split store -------
__global__ void gather1() {
    int t = blockIdx.x * blockDim.x + threadIdx.x;
    int w = t >> 5, lane = t & 31;
    if (w >= N_NODES*H1) return;
    int n = w >> 3, h = w & 7;
    int beg = g_rowptr[n], end = g_rowptr[n + 1];
    float as = g_as1[n*H1 + h];

    const int half = lane >> 4;
    const int fl2 = (lane & 15) * 2;
    const __half2* projh = g_P1h + h*(F1/2) + fl2;
    float a0 = 0.f, a1v = 0.f, a2v = 0.f, a3 = 0.f, den = 0.f;
    for (int base = beg; base < end; base += 32) {
        int i = base + lane;
        int s = 0; float wgt = 0.f;
        if (i < end) {
            s = g_nbr[i];
            float v = as + g_an1[s*H1 + h];
            v = (v >= 0.f) ? v : NEG_SLOPE*v;
            wgt = __expf(v);
            den += wgt;
        }
        int cnt = min(32, end - base);
        if (cnt == 32) {
#pragma unroll
            for (int j = 0; j < 16; j++) {
                int sl = 2*j + half;
                float ww = __shfl_sync(FULL, wgt, sl);
                int ss = __shfl_sync(FULL, s, sl);
                uint2 u = *(const uint2*)&projh[(size_t)ss*(C1/2)];
                float2 f0 = __half22float2(*reinterpret_cast<__half2*>(&u.x));
                float2 f1 = __half22float2(*reinterpret_cast<__half2*>(&u.y));
                a0 += ww*f0.x; a1v += ww*f0.y; a2v += ww*f1.x; a3 += ww*f1.y;
            }
        } else {
            int jmax = (cnt + 1) >> 1;
            for (int j = 0; j < jmax; j++) {
                int sl = 2*j + half;
                float ww = __shfl_sync(FULL, wgt, sl);
                int ss = __shfl_sync(FULL, s, sl);
                uint2 u = *(const uint2*)&projh[(size_t)ss*(C1/2)];
                float2 f0 = __half22float2(*reinterpret_cast<__half2*>(&u.x));
                float2 f1 = __half22float2(*reinterpret_cast<__half2*>(&u.y));
                a0 += ww*f0.x; a1v += ww*f0.y; a2v += ww*f1.x; a3 += ww*f1.y;
            }
        }
    }
    a0  += __shfl_xor_sync(FULL, a0, 16);
    a1v += __shfl_xor_sync(FULL, a1v, 16);
    a2v += __shfl_xor_sync(FULL, a2v, 16);
    a3  += __shfl_xor_sync(FULL, a3, 16);
#pragma unroll
    for (int o = 16; o; o >>= 1) den += __shfl_xor_sync(FULL, den, o);
    if (lane < 16) {
        float inv = 1.f / den;
        a0 *= inv; a1v *= inv; a2v *= inv; a3 *= inv;
        a0  = (a0  > 0.f) ? a0  : expm1f(a0);
        a1v = (a1v > 0.f) ? a1v : expm1f(a1v);
        a2v = (a2v > 0.f) ? a2v : expm1f(a2v);
        a3  = (a3  > 0.f) ? a3  : expm1f(a3);
        // store fp16-split hbuf (feeds gemm2 MMA); kp0 is 8B aligned
        size_t kp0 = (size_t)n*(C1/2) + ((h*F1 + fl2*2) >> 1);
        uint32_t h0, l0, h1, l1;
        split_pack_f16(a0, a1v, h0, l0);
        split_pack_f16(a2v, a3, h1, l1);
        *(uint2*)&g_HH[kp0] = make_uint2(h0, h1);
        *(uint2*)&g_HL[kp0] = make_uint2(l0, l1);
    }
}

// ---------------- fused gather layer 2 (single-pass, fp32 features) ----------
__global__ void gather2(float* __restrict__ out) {
    int t = blockIdx.x * blockDim.x + threadIdx.x;
    int w = t >> 5, lane = t & 31;
    if (w >= N_NODES) return;
    int n = w;
    int beg = g_rowptr[n], end = g_rowptr[n + 1];
    float as = g_as2[n];

    const int half = lane >> 4;
    const int fl = (lane & 15) * 4;
    const float* projl = g_proj2 + fl;
    float a0 = 0.f, a1v = 0.f, a2v = 0.f, a3 = 0.f, den = 0.f;
    for (int base = beg; base < end; base += 32) {
        int i = base + lane;
        int s = 0; float wgt = 0.f;
        if (i < end) {
            s = g_nbr[i];
            float v = as + g_an2[s];
            v = (v >= 0.f) ? v : NEG_SLOPE*v;
            wgt = __expf(v);
            den += wgt;
        }
        int cnt = min(32, end - base);
        if (cnt == 32) {
#pragma unroll
            for (int j = 0; j < 16; j++) {
                int sl = 2*j + half;
                float ww = __shfl_sync(FULL, wgt, sl);
                int ss = __shfl_sync(FULL, s, sl);
                float4 p = *(const float4*)&projl[(size_t)ss*F2];
                a0 += ww*p.x; a1v += ww*p.y; a2v += ww*p.z; a3 += ww*p.w;
            }
        } else {
            int jmax = (cnt + 1) >> 1;
            for (int j = 0; j < jmax; j++) {
                int sl = 2*j + half;
                float ww = __shfl_sync(FULL, wgt, sl);
                int ss = __shfl_sync(FULL, s, sl);
                float4 p = *(const float4*)&projl[(size_t)ss*F2];
                a0 += ww*p.x; a1v += ww*p.y; a2v += ww*p.z; a3 += ww*p.w;
            }
        }
    }
    a0  += __shfl_xor_sync(FULL, a0, 16);
    a1v += __shfl_xor_sync(FULL, a1v, 16);
    a2v += __shfl_xor_sync(FULL, a2v, 16);
    a3  += __shfl_xor_sync(FULL, a3, 16);
#pragma unroll
    for (int o = 16; o; o >>= 1) den += __shfl_xor_sync(FULL, den, o);
    if (lane < 16) {
        float inv = 1.f / den;
        *(float4*)&out[(size_t)n*F2 + fl] =
            make_float4(a0*inv, a1v*inv, a2v*inv, a3*inv);
    }
}

// ---------------- launch -------------------------------------------------------
extern "C" void kernel_launch(void* const* d_in, const int* in_sizes, int n_in,
                              void* d_out, int out_size) {
    const float* x     = (const float*)d_in[0];
    const int*   edges = (const int*)d_in[1];
    const float* W1    = (const float*)d_in[2];
    const float* a1    = (const float*)d_in[3];
    const float* W2    = (const float*)d_in[4];
    const float* a2    = (const float*)d_in[5];
    float* out = (float*)d_out;

    static cudaStream_t s2 = nullptr;
    static cudaEvent_t evFork = nullptr, evCSR = nullptr;
    if (s2 == nullptr) {
        cudaStreamCreateWithFlags(&s2, cudaStreamNonBlocking);
        cudaEventCreateWithFlags(&evFork, cudaEventDisableTiming);
        cudaEventCreateWithFlags(&evCSR, cudaEventDisableTiming);
    }

    void* cnt_ptr = nullptr;
    cudaGetSymbolAddress(&cnt_ptr, g_cnt);

    // fork: CSR build on s2, concurrent with split+gemm1 on main stream
    cudaEventRecord(evFork, 0);
    cudaStreamWaitEvent(s2, evFork, 0);

    cudaMemsetAsync(cnt_ptr, 0, N_NODES*sizeof(int), s2);
    prep_edges<<<(NE + 255)/256, 256, 0, s2>>>(edges);
    scan_kernel<<<1, 1024, 0, s2>>>();
    fill_csr<<<(NE + 255)/256, 256, 0, s2>>>();
    cudaEventRecord(evCSR, s2);

    prep_splits<<<(NXP/2 + 255)/256, 256>>>(W1, W2, x);
    gemm1_kernel<<<dim3(H1, (N_NODES + 127)/128), 256>>>(a1);

    // join: gather1 needs CSR + gemm1
    cudaStreamWaitEvent(0, evCSR, 0);
    gather1<<<(N_NODES*H1*32 + 255)/256, 256>>>();

    // layer 2
    gemm2_kernel<<<dim3(ZK2, (N_NODES + 127)/128), 256>>>();
    alpha2_combine<<<(N_NODES*32 + 255)/256, 256>>>(a2);
    gather2<<<(N_NODES*32 + 255)/256, 256>>>(out);
}